// round 1
// baseline (speedup 1.0000x reference)
#include <cuda_runtime.h>
#include <cstdint>

// Problem constants (shapes fixed by the reference)
constexpr int NF = 512;   // input features
constexpr int NH = 256;   // hidden
constexpr int NC = 64;    // classes
constexpr int NNODE = 100000;

// Scratch (allocation-free rule: __device__ globals)
__device__ float g_xw1[(size_t)NNODE * NH];  // x @ W1
__device__ float g_ag1[(size_t)NNODE * NH];  // spmm1 accumulator / h
__device__ float g_hw2[(size_t)NNODE * NC];  // h @ W2
__device__ float g_ag2[(size_t)NNODE * NC];  // spmm2 accumulator

// ---------------------------------------------------------------------------
// vector fp32 reduction to global (sm_90+)
__device__ __forceinline__ void red_add_v4(float4* addr, float4 v) {
    asm volatile("red.global.add.v4.f32 [%0], {%1,%2,%3,%4};"
                 :: "l"(addr), "f"(v.x), "f"(v.y), "f"(v.z), "f"(v.w)
                 : "memory");
}

// ---------------------------------------------------------------------------
__global__ void zero_kernel(float4* __restrict__ p, int n4) {
    int i = blockIdx.x * blockDim.x + threadIdx.x;
    if (i < n4) p[i] = make_float4(0.f, 0.f, 0.f, 0.f);
}

// ---------------------------------------------------------------------------
// 64x64 tile SGEMM, BK=16, 256 threads, 4x4 per thread.
// Requires N % 64 == 0, K % 16 == 0 (true for both GEMMs). M guarded.
__global__ void sgemm64(const float* __restrict__ A, const float* __restrict__ B,
                        float* __restrict__ C, int M, int N, int K) {
    __shared__ __align__(16) float As[16][68];  // [k][m], padded (272B rows keep 16B align)
    __shared__ __align__(16) float Bs[16][64];  // [k][n]

    const int tid = threadIdx.x;
    const int tx = tid & 15;          // 0..15 -> 4 cols each
    const int ty = tid >> 4;          // 0..15 -> 4 rows each
    const int rowBase = blockIdx.y * 64;
    const int colBase = blockIdx.x * 64;

    const int arow = tid >> 2;          // 0..63
    const int acol = (tid & 3) * 4;     // 0,4,8,12
    const int brow = tid >> 4;          // 0..15
    const int bcol = (tid & 15) * 4;    // 0..60

    float acc[4][4];
#pragma unroll
    for (int i = 0; i < 4; i++)
#pragma unroll
        for (int j = 0; j < 4; j++) acc[i][j] = 0.f;

    for (int k0 = 0; k0 < K; k0 += 16) {
        // load A tile (64 x 16), transpose into As[k][m]
        float4 a = make_float4(0.f, 0.f, 0.f, 0.f);
        int gr = rowBase + arow;
        if (gr < M) a = *(const float4*)(A + (size_t)gr * K + k0 + acol);
        As[acol + 0][arow] = a.x;
        As[acol + 1][arow] = a.y;
        As[acol + 2][arow] = a.z;
        As[acol + 3][arow] = a.w;
        // load B tile (16 x 64)
        float4 b = *(const float4*)(B + (size_t)(k0 + brow) * N + colBase + bcol);
        *(float4*)&Bs[brow][bcol] = b;
        __syncthreads();

#pragma unroll
        for (int k = 0; k < 16; k++) {
            float4 av = *(const float4*)&As[k][ty * 4];
            float4 bv = *(const float4*)&Bs[k][tx * 4];
            float avv[4] = {av.x, av.y, av.z, av.w};
            float bvv[4] = {bv.x, bv.y, bv.z, bv.w};
#pragma unroll
            for (int i = 0; i < 4; i++)
#pragma unroll
                for (int j = 0; j < 4; j++)
                    acc[i][j] = fmaf(avv[i], bvv[j], acc[i][j]);
        }
        __syncthreads();
    }

#pragma unroll
    for (int i = 0; i < 4; i++) {
        int gr = rowBase + ty * 4 + i;
        if (gr < M) {
            float4 o = make_float4(acc[i][0], acc[i][1], acc[i][2], acc[i][3]);
            *(float4*)(C + (size_t)gr * N + colBase + tx * 4) = o;
        }
    }
}

// ---------------------------------------------------------------------------
// SpMM F=256: one warp per edge; each lane handles 2 float4 (8 floats).
__global__ void spmm_f256(const int* __restrict__ rows, const int* __restrict__ cols,
                          const float* __restrict__ vals, const float* __restrict__ X,
                          float* __restrict__ Y, int E) {
    int warp = (blockIdx.x * blockDim.x + threadIdx.x) >> 5;
    int lane = threadIdx.x & 31;
    if (warp >= E) return;
    int r = rows[warp];
    int c = cols[warp];
    float v = vals[warp];
    const float4* src = (const float4*)(X + (size_t)c * 256);
    float4* dst = (float4*)(Y + (size_t)r * 256);
#pragma unroll
    for (int i = 0; i < 2; i++) {
        float4 m = __ldg(&src[lane + 32 * i]);
        m.x *= v; m.y *= v; m.z *= v; m.w *= v;
        red_add_v4(&dst[lane + 32 * i], m);
    }
}

// SpMM F=64: 16 threads per edge; each thread one float4.
__global__ void spmm_f64(const int* __restrict__ rows, const int* __restrict__ cols,
                         const float* __restrict__ vals, const float* __restrict__ X,
                         float* __restrict__ Y, int E) {
    int t = blockIdx.x * blockDim.x + threadIdx.x;
    int e = t >> 4;
    int q = t & 15;
    if (e >= E) return;
    int r = rows[e];
    int c = cols[e];
    float v = vals[e];
    const float4* src = (const float4*)(X + (size_t)c * 64);
    float4* dst = (float4*)(Y + (size_t)r * 64);
    float4 m = __ldg(&src[q]);
    m.x *= v; m.y *= v; m.z *= v; m.w *= v;
    red_add_v4(&dst[q], m);
}

// ---------------------------------------------------------------------------
// In-place bias + relu over [M, NH] viewed as float4
__global__ void bias_relu(float4* __restrict__ Y, const float* __restrict__ b,
                          int total4, int F4) {
    int i = blockIdx.x * blockDim.x + threadIdx.x;
    if (i >= total4) return;
    float4 v = Y[i];
    float4 bb = __ldg((const float4*)b + (i % F4));
    v.x = fmaxf(v.x + bb.x, 0.f);
    v.y = fmaxf(v.y + bb.y, 0.f);
    v.z = fmaxf(v.z + bb.z, 0.f);
    v.w = fmaxf(v.w + bb.w, 0.f);
    Y[i] = v;
}

// ---------------------------------------------------------------------------
// bias + log_softmax over 64 classes; one warp per node (2 values/lane)
__global__ void bias_logsoftmax64(const float* __restrict__ in, const float* __restrict__ b,
                                  float* __restrict__ out, int M) {
    int warp = (blockIdx.x * blockDim.x + threadIdx.x) >> 5;
    int lane = threadIdx.x & 31;
    if (warp >= M) return;
    const float* r = in + (size_t)warp * 64;
    float v0 = r[lane] + __ldg(&b[lane]);
    float v1 = r[lane + 32] + __ldg(&b[lane + 32]);
    float m = fmaxf(v0, v1);
#pragma unroll
    for (int o = 16; o; o >>= 1) m = fmaxf(m, __shfl_xor_sync(0xffffffffu, m, o));
    float s = __expf(v0 - m) + __expf(v1 - m);
#pragma unroll
    for (int o = 16; o; o >>= 1) s += __shfl_xor_sync(0xffffffffu, s, o);
    float lse = m + __logf(s);
    float* w = out + (size_t)warp * 64;
    w[lane] = v0 - lse;
    w[lane + 32] = v1 - lse;
}

// ---------------------------------------------------------------------------
extern "C" void kernel_launch(void* const* d_in, const int* in_sizes, int n_in,
                              void* d_out, int out_size) {
    const float* x    = (const float*)d_in[0];
    const int*   erow = (const int*)d_in[1];
    const int*   ecol = (const int*)d_in[2];
    const float* eval_ = (const float*)d_in[3];
    const float* W1   = (const float*)d_in[4];
    const float* b1   = (const float*)d_in[5];
    const float* W2   = (const float*)d_in[6];
    const float* b2   = (const float*)d_in[7];
    float* out = (float*)d_out;

    const int E = in_sizes[1];
    const int M = in_sizes[0] / NF;  // 100000

    float *xw1, *ag1, *hw2, *ag2;
    cudaGetSymbolAddress((void**)&xw1, g_xw1);
    cudaGetSymbolAddress((void**)&ag1, g_ag1);
    cudaGetSymbolAddress((void**)&hw2, g_hw2);
    cudaGetSymbolAddress((void**)&ag2, g_ag2);

    // zero accumulators
    {
        int n4 = M * NH / 4;
        zero_kernel<<<(n4 + 255) / 256, 256>>>((float4*)ag1, n4);
        int m4 = M * NC / 4;
        zero_kernel<<<(m4 + 255) / 256, 256>>>((float4*)ag2, m4);
    }

    // layer 1: XW1 = x @ W1
    sgemm64<<<dim3(NH / 64, (M + 63) / 64), 256>>>(x, W1, xw1, M, NH, NF);

    // spmm1: ag1 += scatter(val * XW1[col])
    {
        long long threads = (long long)E * 32;
        int blocks = (int)((threads + 255) / 256);
        spmm_f256<<<blocks, 256>>>(erow, ecol, eval_, xw1, ag1, E);
    }

    // bias + relu in place -> h
    {
        int n4 = M * NH / 4;
        bias_relu<<<(n4 + 255) / 256, 256>>>((float4*)ag1, b1, n4, NH / 4);
    }

    // layer 2: HW2 = h @ W2
    sgemm64<<<dim3(NC / 64, (M + 63) / 64), 256>>>(ag1, W2, hw2, M, NC, NH);

    // spmm2
    {
        long long threads = (long long)E * 16;
        int blocks = (int)((threads + 255) / 256);
        spmm_f64<<<blocks, 256>>>(erow, ecol, eval_, hw2, ag2, E);
    }

    // bias + log_softmax -> out
    {
        long long threads = (long long)M * 32;
        int blocks = (int)((threads + 255) / 256);
        bias_logsoftmax64<<<blocks, 256>>>(ag2, b2, out, M);
    }
}

// round 2
// speedup vs baseline: 1.0853x; 1.0853x over previous
#include <cuda_runtime.h>
#include <cstdint>

// Problem constants (shapes fixed by the reference)
constexpr int NF = 512;   // input features
constexpr int NH = 256;   // hidden
constexpr int NC = 64;    // classes
constexpr int NNODE = 100000;

// Scratch (allocation-free rule: __device__ globals)
__device__ float g_xw1[(size_t)NNODE * NH];  // x @ W1
__device__ float g_ag1[(size_t)NNODE * NH];  // spmm1 accumulator / h
__device__ float g_hw2[(size_t)NNODE * NC];  // h @ W2
__device__ float g_ag2[(size_t)NNODE * NC];  // spmm2 accumulator

// ---------------------------------------------------------------------------
// vector fp32 reduction to global (sm_90+)
__device__ __forceinline__ void red_add_v4(float4* addr, float4 v) {
    asm volatile("red.global.add.v4.f32 [%0], {%1,%2,%3,%4};"
                 :: "l"(addr), "f"(v.x), "f"(v.y), "f"(v.z), "f"(v.w)
                 : "memory");
}

// ---------------------------------------------------------------------------
__global__ void zero_kernel(float4* __restrict__ p, int n4) {
    int i = blockIdx.x * blockDim.x + threadIdx.x;
    if (i < n4) p[i] = make_float4(0.f, 0.f, 0.f, 0.f);
}

// ---------------------------------------------------------------------------
// 128x64 tile SGEMM, BK=16, 256 threads, 8x4 per thread.
// Requires N % 64 == 0, K % 16 == 0 (true for both GEMMs). M guarded.
__global__ __launch_bounds__(256) void sgemm128x64(
        const float* __restrict__ A, const float* __restrict__ B,
        float* __restrict__ C, int M, int N, int K) {
    __shared__ __align__(16) float As[16][132];  // [k][m], padded (528B rows keep 16B align)
    __shared__ __align__(16) float Bs[16][64];   // [k][n]

    const int tid = threadIdx.x;
    const int tx = tid & 15;          // 0..15 -> 4 cols each
    const int ty = tid >> 4;          // 0..15 -> 8 rows each
    const int rowBase = blockIdx.y * 128;
    const int colBase = blockIdx.x * 64;

    // A tile load map: 128 rows x 16 cols; each thread loads 8 contiguous floats
    const int arow = tid >> 1;             // 0..127
    const int acol = (tid & 1) * 8;        // 0 or 8
    // B tile load map: 16 rows x 64 cols; each thread one float4
    const int brow = tid >> 4;             // 0..15
    const int bcol = (tid & 15) * 4;       // 0..60

    float acc[8][4];
#pragma unroll
    for (int i = 0; i < 8; i++)
#pragma unroll
        for (int j = 0; j < 4; j++) acc[i][j] = 0.f;

    for (int k0 = 0; k0 < K; k0 += 16) {
        // load A tile (128 x 16), transpose into As[k][m]
        float4 a0 = make_float4(0.f, 0.f, 0.f, 0.f);
        float4 a1 = make_float4(0.f, 0.f, 0.f, 0.f);
        int gr = rowBase + arow;
        if (gr < M) {
            const float4* ap = (const float4*)(A + (size_t)gr * K + k0 + acol);
            a0 = ap[0];
            a1 = ap[1];
        }
        As[acol + 0][arow] = a0.x;
        As[acol + 1][arow] = a0.y;
        As[acol + 2][arow] = a0.z;
        As[acol + 3][arow] = a0.w;
        As[acol + 4][arow] = a1.x;
        As[acol + 5][arow] = a1.y;
        As[acol + 6][arow] = a1.z;
        As[acol + 7][arow] = a1.w;
        // load B tile (16 x 64)
        *(float4*)&Bs[brow][bcol] =
            *(const float4*)(B + (size_t)(k0 + brow) * N + colBase + bcol);
        __syncthreads();

#pragma unroll
        for (int k = 0; k < 16; k++) {
            float4 av0 = *(const float4*)&As[k][ty * 8];
            float4 av1 = *(const float4*)&As[k][ty * 8 + 4];
            float4 bv  = *(const float4*)&Bs[k][tx * 4];
            float avv[8] = {av0.x, av0.y, av0.z, av0.w, av1.x, av1.y, av1.z, av1.w};
            float bvv[4] = {bv.x, bv.y, bv.z, bv.w};
#pragma unroll
            for (int i = 0; i < 8; i++)
#pragma unroll
                for (int j = 0; j < 4; j++)
                    acc[i][j] = fmaf(avv[i], bvv[j], acc[i][j]);
        }
        __syncthreads();
    }

#pragma unroll
    for (int i = 0; i < 8; i++) {
        int gr = rowBase + ty * 8 + i;
        if (gr < M) {
            float4 o = make_float4(acc[i][0], acc[i][1], acc[i][2], acc[i][3]);
            *(float4*)(C + (size_t)gr * N + colBase + tx * 4) = o;
        }
    }
}

// ---------------------------------------------------------------------------
// SpMM F=256, feature-chunked: one warp per edge; each lane handles one float4
// within a 128-feature chunk (32 lanes * 4 = 128). `off4` = chunk offset in
// float4 units (0 or 32). Chunking keeps the per-pass working set
// (51.2 MB src + 51.2 MB dst) L2-resident.
__global__ void spmm_f256_chunk(const int* __restrict__ rows, const int* __restrict__ cols,
                                const float* __restrict__ vals, const float* __restrict__ X,
                                float* __restrict__ Y, int E, int off4) {
    int warp = (blockIdx.x * blockDim.x + threadIdx.x) >> 5;
    int lane = threadIdx.x & 31;
    if (warp >= E) return;
    int r = rows[warp];
    int c = cols[warp];
    float v = vals[warp];
    const float4* src = (const float4*)(X + (size_t)c * 256) + off4 + lane;
    float4* dst = (float4*)(Y + (size_t)r * 256) + off4 + lane;
    float4 m = __ldg(src);
    m.x *= v; m.y *= v; m.z *= v; m.w *= v;
    red_add_v4(dst, m);
}

// SpMM F=64: 16 threads per edge; each thread one float4.
__global__ void spmm_f64(const int* __restrict__ rows, const int* __restrict__ cols,
                         const float* __restrict__ vals, const float* __restrict__ X,
                         float* __restrict__ Y, int E) {
    int t = blockIdx.x * blockDim.x + threadIdx.x;
    int e = t >> 4;
    int q = t & 15;
    if (e >= E) return;
    int r = rows[e];
    int c = cols[e];
    float v = vals[e];
    const float4* src = (const float4*)(X + (size_t)c * 64);
    float4* dst = (float4*)(Y + (size_t)r * 64);
    float4 m = __ldg(&src[q]);
    m.x *= v; m.y *= v; m.z *= v; m.w *= v;
    red_add_v4(&dst[q], m);
}

// ---------------------------------------------------------------------------
// In-place bias + relu over [M, NH] viewed as float4
__global__ void bias_relu(float4* __restrict__ Y, const float* __restrict__ b,
                          int total4, int F4) {
    int i = blockIdx.x * blockDim.x + threadIdx.x;
    if (i >= total4) return;
    float4 v = Y[i];
    float4 bb = __ldg((const float4*)b + (i % F4));
    v.x = fmaxf(v.x + bb.x, 0.f);
    v.y = fmaxf(v.y + bb.y, 0.f);
    v.z = fmaxf(v.z + bb.z, 0.f);
    v.w = fmaxf(v.w + bb.w, 0.f);
    Y[i] = v;
}

// ---------------------------------------------------------------------------
// bias + log_softmax over 64 classes; one warp per node (2 values/lane)
__global__ void bias_logsoftmax64(const float* __restrict__ in, const float* __restrict__ b,
                                  float* __restrict__ out, int M) {
    int warp = (blockIdx.x * blockDim.x + threadIdx.x) >> 5;
    int lane = threadIdx.x & 31;
    if (warp >= M) return;
    const float* r = in + (size_t)warp * 64;
    float v0 = r[lane] + __ldg(&b[lane]);
    float v1 = r[lane + 32] + __ldg(&b[lane + 32]);
    float m = fmaxf(v0, v1);
#pragma unroll
    for (int o = 16; o; o >>= 1) m = fmaxf(m, __shfl_xor_sync(0xffffffffu, m, o));
    float s = __expf(v0 - m) + __expf(v1 - m);
#pragma unroll
    for (int o = 16; o; o >>= 1) s += __shfl_xor_sync(0xffffffffu, s, o);
    float lse = m + __logf(s);
    float* w = out + (size_t)warp * 64;
    w[lane] = v0 - lse;
    w[lane + 32] = v1 - lse;
}

// ---------------------------------------------------------------------------
extern "C" void kernel_launch(void* const* d_in, const int* in_sizes, int n_in,
                              void* d_out, int out_size) {
    const float* x    = (const float*)d_in[0];
    const int*   erow = (const int*)d_in[1];
    const int*   ecol = (const int*)d_in[2];
    const float* eval_ = (const float*)d_in[3];
    const float* W1   = (const float*)d_in[4];
    const float* b1   = (const float*)d_in[5];
    const float* W2   = (const float*)d_in[6];
    const float* b2   = (const float*)d_in[7];
    float* out = (float*)d_out;

    const int E = in_sizes[1];
    const int M = in_sizes[0] / NF;  // 100000

    float *xw1, *ag1, *hw2, *ag2;
    cudaGetSymbolAddress((void**)&xw1, g_xw1);
    cudaGetSymbolAddress((void**)&ag1, g_ag1);
    cudaGetSymbolAddress((void**)&hw2, g_hw2);
    cudaGetSymbolAddress((void**)&ag2, g_ag2);

    // zero accumulators
    {
        int n4 = M * NH / 4;
        zero_kernel<<<(n4 + 255) / 256, 256>>>((float4*)ag1, n4);
        int m4 = M * NC / 4;
        zero_kernel<<<(m4 + 255) / 256, 256>>>((float4*)ag2, m4);
    }

    // layer 1: XW1 = x @ W1
    sgemm128x64<<<dim3(NH / 64, (M + 127) / 128), 256>>>(x, W1, xw1, M, NH, NF);

    // spmm1: ag1 += scatter(val * XW1[col]) — 2 feature chunks of 128 for L2 residency
    {
        long long threads = (long long)E * 32;
        int blocks = (int)((threads + 255) / 256);
        spmm_f256_chunk<<<blocks, 256>>>(erow, ecol, eval_, xw1, ag1, E, 0);
        spmm_f256_chunk<<<blocks, 256>>>(erow, ecol, eval_, xw1, ag1, E, 32);
    }

    // bias + relu in place -> h
    {
        int n4 = M * NH / 4;
        bias_relu<<<(n4 + 255) / 256, 256>>>((float4*)ag1, b1, n4, NH / 4);
    }

    // layer 2: HW2 = h @ W2
    sgemm128x64<<<dim3(NC / 64, (M + 127) / 128), 256>>>(ag1, W2, hw2, M, NC, NH);

    // spmm2
    {
        long long threads = (long long)E * 16;
        int blocks = (int)((threads + 255) / 256);
        spmm_f64<<<blocks, 256>>>(erow, ecol, eval_, hw2, ag2, E);
    }

    // bias + log_softmax -> out
    {
        long long threads = (long long)M * 32;
        int blocks = (int)((threads + 255) / 256);
        bias_logsoftmax64<<<blocks, 256>>>(ag2, b2, out, M);
    }
}

// round 3
// speedup vs baseline: 1.4186x; 1.3071x over previous
#include <cuda_runtime.h>
#include <cstdint>

// Problem constants (shapes fixed by the reference)
constexpr int NF = 512;   // input features
constexpr int NH = 256;   // hidden
constexpr int NC = 64;    // classes
constexpr int NNODE = 100000;

// Scratch (allocation-free rule: __device__ globals)
__device__ float g_xw1[(size_t)NNODE * NH];  // x @ W1
__device__ float g_ag1[(size_t)NNODE * NH];  // spmm1 accumulator / h
__device__ float g_hw2[(size_t)NNODE * NC];  // h @ W2
__device__ float g_ag2[(size_t)NNODE * NC];  // spmm2 accumulator

// ---------------------------------------------------------------------------
__device__ __forceinline__ void red_add_v4(float4* addr, float4 v) {
    asm volatile("red.global.add.v4.f32 [%0], {%1,%2,%3,%4};"
                 :: "l"(addr), "f"(v.x), "f"(v.y), "f"(v.z), "f"(v.w)
                 : "memory");
}

__device__ __forceinline__ uint32_t f2tf32(float f) {
    uint32_t r;
    asm("cvt.rna.tf32.f32 %0, %1;" : "=r"(r) : "f"(f));
    return r;
}

__device__ __forceinline__ void mma_tf32(float c[4], const uint32_t a[4], const uint32_t b[2]) {
    asm volatile(
        "mma.sync.aligned.m16n8k8.row.col.f32.tf32.tf32.f32 "
        "{%0,%1,%2,%3}, {%4,%5,%6,%7}, {%8,%9}, {%0,%1,%2,%3};"
        : "+f"(c[0]), "+f"(c[1]), "+f"(c[2]), "+f"(c[3])
        : "r"(a[0]), "r"(a[1]), "r"(a[2]), "r"(a[3]), "r"(b[0]), "r"(b[1]));
}

// ---------------------------------------------------------------------------
__global__ void zero_kernel(float4* __restrict__ p, int n4) {
    int i = blockIdx.x * blockDim.x + threadIdx.x;
    if (i < n4) p[i] = make_float4(0.f, 0.f, 0.f, 0.f);
}

// ---------------------------------------------------------------------------
// TF32 tensor-core GEMM: C[M,N] = A[M,K] @ B[K,N].
// BM=128, BK=32, 256 threads (8 warps) arranged WARPS_M x WARPS_N.
// Requires N % BN == 0, K % 32 == 0. M guarded.
template<int BN, int WARPS_M, int WARPS_N>
__global__ __launch_bounds__(256) void tf32_gemm(
        const float* __restrict__ A, const float* __restrict__ B,
        float* __restrict__ C, int M, int N, int K) {
    constexpr int BM = 128;
    constexpr int BK = 32;
    constexpr int WM = BM / WARPS_M;     // warp tile m
    constexpr int WN = BN / WARPS_N;     // warp tile n
    constexpr int MFR = WM / 16;         // m16 frags per warp
    constexpr int NFR = WN / 8;          // n8 frags per warp
    constexpr int ASTRIDE = BK + 4;      // 36: bank = (4m + k) % 32, conflict-free frags
    constexpr int BSTRIDE = BN + 8;      // bank = (8k + n) % 32, conflict-free frags

    __shared__ uint32_t As[BM][ASTRIDE];
    __shared__ uint32_t Bs[BK][BSTRIDE];

    const int tid  = threadIdx.x;
    const int warp = tid >> 5;
    const int lane = tid & 31;
    const int wm = (warp % WARPS_M) * WM;
    const int wn = (warp / WARPS_M) * WN;
    const int rowBase = blockIdx.y * BM;
    const int colBase = blockIdx.x * BN;

    float acc[MFR][NFR][4];
#pragma unroll
    for (int i = 0; i < MFR; i++)
#pragma unroll
        for (int j = 0; j < NFR; j++)
#pragma unroll
            for (int q = 0; q < 4; q++) acc[i][j][q] = 0.f;

    // A tile map: 128 rows x 32 cols, 2 threads/row, 4 float4 each
    const int arow = tid >> 1;
    const int acol0 = (tid & 1) * 16;
    // B tile map: 32 rows x BN cols, 8 threads/row, BN/32 float4 each
    const int brow = tid >> 3;
    const int bf40 = tid & 7;

    for (int k0 = 0; k0 < K; k0 += BK) {
        // --- load A tile ---
        {
            const int gr = rowBase + arow;
            const float* ap = A + (size_t)gr * K + k0 + acol0;
#pragma unroll
            for (int i = 0; i < 4; i++) {
                float4 a = make_float4(0.f, 0.f, 0.f, 0.f);
                if (gr < M) a = *(const float4*)(ap + i * 4);
                const int c = acol0 + i * 4;
                As[arow][c + 0] = f2tf32(a.x);
                As[arow][c + 1] = f2tf32(a.y);
                As[arow][c + 2] = f2tf32(a.z);
                As[arow][c + 3] = f2tf32(a.w);
            }
        }
        // --- load B tile ---
        {
            const float* bp = B + (size_t)(k0 + brow) * N + colBase;
#pragma unroll
            for (int i = 0; i < BN / 32; i++) {
                const int f4 = bf40 + i * 8;
                float4 b = *(const float4*)(bp + f4 * 4);
                Bs[brow][f4 * 4 + 0] = f2tf32(b.x);
                Bs[brow][f4 * 4 + 1] = f2tf32(b.y);
                Bs[brow][f4 * 4 + 2] = f2tf32(b.z);
                Bs[brow][f4 * 4 + 3] = f2tf32(b.w);
            }
        }
        __syncthreads();

#pragma unroll
        for (int ks = 0; ks < BK / 8; ks++) {
            uint32_t afr[MFR][4];
            uint32_t bfr[NFR][2];
            const int ar = wm + (lane >> 2);
            const int ac = ks * 8 + (lane & 3);
#pragma unroll
            for (int mi = 0; mi < MFR; mi++) {
                afr[mi][0] = As[ar + mi * 16 + 0][ac + 0];
                afr[mi][1] = As[ar + mi * 16 + 8][ac + 0];
                afr[mi][2] = As[ar + mi * 16 + 0][ac + 4];
                afr[mi][3] = As[ar + mi * 16 + 8][ac + 4];
            }
            const int br = ks * 8 + (lane & 3);
            const int bc = wn + (lane >> 2);
#pragma unroll
            for (int ni = 0; ni < NFR; ni++) {
                bfr[ni][0] = Bs[br + 0][bc + ni * 8];
                bfr[ni][1] = Bs[br + 4][bc + ni * 8];
            }
#pragma unroll
            for (int mi = 0; mi < MFR; mi++)
#pragma unroll
                for (int ni = 0; ni < NFR; ni++)
                    mma_tf32(acc[mi][ni], afr[mi], bfr[ni]);
        }
        __syncthreads();
    }

    // --- epilogue ---
#pragma unroll
    for (int mi = 0; mi < MFR; mi++) {
#pragma unroll
        for (int ni = 0; ni < NFR; ni++) {
            const int r0 = rowBase + wm + mi * 16 + (lane >> 2);
            const int c0 = colBase + wn + ni * 8 + 2 * (lane & 3);
            if (r0 < M)
                *(float2*)(C + (size_t)r0 * N + c0) = make_float2(acc[mi][ni][0], acc[mi][ni][1]);
            if (r0 + 8 < M)
                *(float2*)(C + (size_t)(r0 + 8) * N + c0) = make_float2(acc[mi][ni][2], acc[mi][ni][3]);
        }
    }
}

// ---------------------------------------------------------------------------
// SpMM F=256, feature-chunked: one warp per edge; each lane one float4 within
// a 128-feature chunk. Chunking keeps per-pass working set L2-resident.
__global__ void spmm_f256_chunk(const int* __restrict__ rows, const int* __restrict__ cols,
                                const float* __restrict__ vals, const float* __restrict__ X,
                                float* __restrict__ Y, int E, int off4) {
    int warp = (blockIdx.x * blockDim.x + threadIdx.x) >> 5;
    int lane = threadIdx.x & 31;
    if (warp >= E) return;
    int r = rows[warp];
    int c = cols[warp];
    float v = vals[warp];
    const float4* src = (const float4*)(X + (size_t)c * 256) + off4 + lane;
    float4* dst = (float4*)(Y + (size_t)r * 256) + off4 + lane;
    float4 m = __ldg(src);
    m.x *= v; m.y *= v; m.z *= v; m.w *= v;
    red_add_v4(dst, m);
}

// SpMM F=64: 16 threads per edge; each thread one float4.
__global__ void spmm_f64(const int* __restrict__ rows, const int* __restrict__ cols,
                         const float* __restrict__ vals, const float* __restrict__ X,
                         float* __restrict__ Y, int E) {
    int t = blockIdx.x * blockDim.x + threadIdx.x;
    int e = t >> 4;
    int q = t & 15;
    if (e >= E) return;
    int r = rows[e];
    int c = cols[e];
    float v = vals[e];
    const float4* src = (const float4*)(X + (size_t)c * 64);
    float4* dst = (float4*)(Y + (size_t)r * 64);
    float4 m = __ldg(&src[q]);
    m.x *= v; m.y *= v; m.z *= v; m.w *= v;
    red_add_v4(&dst[q], m);
}

// ---------------------------------------------------------------------------
__global__ void bias_relu(float4* __restrict__ Y, const float* __restrict__ b,
                          int total4, int F4) {
    int i = blockIdx.x * blockDim.x + threadIdx.x;
    if (i >= total4) return;
    float4 v = Y[i];
    float4 bb = __ldg((const float4*)b + (i % F4));
    v.x = fmaxf(v.x + bb.x, 0.f);
    v.y = fmaxf(v.y + bb.y, 0.f);
    v.z = fmaxf(v.z + bb.z, 0.f);
    v.w = fmaxf(v.w + bb.w, 0.f);
    Y[i] = v;
}

// ---------------------------------------------------------------------------
__global__ void bias_logsoftmax64(const float* __restrict__ in, const float* __restrict__ b,
                                  float* __restrict__ out, int M) {
    int warp = (blockIdx.x * blockDim.x + threadIdx.x) >> 5;
    int lane = threadIdx.x & 31;
    if (warp >= M) return;
    const float* r = in + (size_t)warp * 64;
    float v0 = r[lane] + __ldg(&b[lane]);
    float v1 = r[lane + 32] + __ldg(&b[lane + 32]);
    float m = fmaxf(v0, v1);
#pragma unroll
    for (int o = 16; o; o >>= 1) m = fmaxf(m, __shfl_xor_sync(0xffffffffu, m, o));
    float s = __expf(v0 - m) + __expf(v1 - m);
#pragma unroll
    for (int o = 16; o; o >>= 1) s += __shfl_xor_sync(0xffffffffu, s, o);
    float lse = m + __logf(s);
    float* w = out + (size_t)warp * 64;
    w[lane] = v0 - lse;
    w[lane + 32] = v1 - lse;
}

// ---------------------------------------------------------------------------
extern "C" void kernel_launch(void* const* d_in, const int* in_sizes, int n_in,
                              void* d_out, int out_size) {
    const float* x    = (const float*)d_in[0];
    const int*   erow = (const int*)d_in[1];
    const int*   ecol = (const int*)d_in[2];
    const float* eval_ = (const float*)d_in[3];
    const float* W1   = (const float*)d_in[4];
    const float* b1   = (const float*)d_in[5];
    const float* W2   = (const float*)d_in[6];
    const float* b2   = (const float*)d_in[7];
    float* out = (float*)d_out;

    const int E = in_sizes[1];
    const int M = in_sizes[0] / NF;  // 100000

    float *xw1, *ag1, *hw2, *ag2;
    cudaGetSymbolAddress((void**)&xw1, g_xw1);
    cudaGetSymbolAddress((void**)&ag1, g_ag1);
    cudaGetSymbolAddress((void**)&hw2, g_hw2);
    cudaGetSymbolAddress((void**)&ag2, g_ag2);

    // zero accumulators
    {
        int n4 = M * NH / 4;
        zero_kernel<<<(n4 + 255) / 256, 256>>>((float4*)ag1, n4);
        int m4 = M * NC / 4;
        zero_kernel<<<(m4 + 255) / 256, 256>>>((float4*)ag2, m4);
    }

    // layer 1: XW1 = x @ W1  (tf32 tensor cores, 128x128 tile)
    tf32_gemm<128, 2, 4><<<dim3(NH / 128, (M + 127) / 128), 256>>>(x, W1, xw1, M, NH, NF);

    // spmm1: ag1 += scatter(val * XW1[col]) — 2 feature chunks of 128 for L2 residency
    {
        long long threads = (long long)E * 32;
        int blocks = (int)((threads + 255) / 256);
        spmm_f256_chunk<<<blocks, 256>>>(erow, ecol, eval_, xw1, ag1, E, 0);
        spmm_f256_chunk<<<blocks, 256>>>(erow, ecol, eval_, xw1, ag1, E, 32);
    }

    // bias + relu in place -> h
    {
        int n4 = M * NH / 4;
        bias_relu<<<(n4 + 255) / 256, 256>>>((float4*)ag1, b1, n4, NH / 4);
    }

    // layer 2: HW2 = h @ W2  (tf32 tensor cores, 128x64 tile)
    tf32_gemm<64, 4, 2><<<dim3(NC / 64, (M + 127) / 128), 256>>>(ag1, W2, hw2, M, NC, NH);

    // spmm2
    {
        long long threads = (long long)E * 16;
        int blocks = (int)((threads + 255) / 256);
        spmm_f64<<<blocks, 256>>>(erow, ecol, eval_, hw2, ag2, E);
    }

    // bias + log_softmax -> out
    {
        long long threads = (long long)M * 32;
        int blocks = (int)((threads + 255) / 256);
        bias_logsoftmax64<<<blocks, 256>>>(ag2, b2, out, M);
    }
}

// round 4
// speedup vs baseline: 2.7775x; 1.9580x over previous
#include <cuda_runtime.h>
#include <cstdint>

// Problem constants (shapes fixed by the reference)
constexpr int NF = 512;   // input features
constexpr int NH = 256;   // hidden
constexpr int NC = 64;    // classes
constexpr int NNODE = 100000;
constexpr int EMAX = 3200000;

// Scratch (allocation-free rule: __device__ globals)
__device__ float g_xw1[(size_t)NNODE * NH];  // x @ W1
__device__ float g_h[(size_t)NNODE * NH];    // spmm1 out / h
__device__ float g_hw2[(size_t)NNODE * NC];  // h @ W2
__device__ int   g_rowptr[NNODE + 1];
__device__ int   g_cursor[NNODE];
__device__ int2  g_edges[EMAX];              // (col, val-bits) sorted by row
__device__ int   g_bsums[128];

// ---------------------------------------------------------------------------
__device__ __forceinline__ uint32_t f2tf32(float f) {
    uint32_t r;
    asm("cvt.rna.tf32.f32 %0, %1;" : "=r"(r) : "f"(f));
    return r;
}

__device__ __forceinline__ void mma_tf32(float c[4], const uint32_t a[4], const uint32_t b[2]) {
    asm volatile(
        "mma.sync.aligned.m16n8k8.row.col.f32.tf32.tf32.f32 "
        "{%0,%1,%2,%3}, {%4,%5,%6,%7}, {%8,%9}, {%0,%1,%2,%3};"
        : "+f"(c[0]), "+f"(c[1]), "+f"(c[2]), "+f"(c[3])
        : "r"(a[0]), "r"(a[1]), "r"(a[2]), "r"(a[3]), "r"(b[0]), "r"(b[1]));
}

__device__ __forceinline__ void stcs4(float4* p, float4 v) {
    asm volatile("st.global.cs.v4.f32 [%0], {%1,%2,%3,%4};"
                 :: "l"(p), "f"(v.x), "f"(v.y), "f"(v.z), "f"(v.w) : "memory");
}

// ---------------------------------------------------------------------------
// CSR build
__global__ void k_zero_csr() {
    int i = blockIdx.x * blockDim.x + threadIdx.x;
    if (i <= NNODE) g_rowptr[i] = 0;
    if (i < NNODE) g_cursor[i] = 0;
}

__global__ void k_hist(const int* __restrict__ rows, int E) {
    int e = blockIdx.x * blockDim.x + threadIdx.x;
    if (e < E) atomicAdd(&g_rowptr[rows[e] + 1], 1);
}

// inclusive block scan: 1024 elements per block (256 threads x 4)
__global__ void k_scan_block(int* __restrict__ d, int L, int* __restrict__ bsums) {
    __shared__ int warpsum[8];
    const int t = threadIdx.x, lane = t & 31, wid = t >> 5;
    const int base = blockIdx.x * 1024 + t * 4;
    int v0 = 0, v1 = 0, v2 = 0, v3 = 0;
    if (base + 3 < L) {
        int4 x = *(const int4*)(d + base);
        v0 = x.x; v1 = x.y; v2 = x.z; v3 = x.w;
    } else {
        if (base < L) v0 = d[base];
        if (base + 1 < L) v1 = d[base + 1];
        if (base + 2 < L) v2 = d[base + 2];
    }
    v1 += v0; v2 += v1; v3 += v2;
    int inc = v3;
#pragma unroll
    for (int o = 1; o < 32; o <<= 1) {
        int n = __shfl_up_sync(0xffffffffu, inc, o);
        if (lane >= o) inc += n;
    }
    if (lane == 31) warpsum[wid] = inc;
    __syncthreads();
    if (wid == 0) {
        int s = (lane < 8) ? warpsum[lane] : 0;
#pragma unroll
        for (int o = 1; o < 8; o <<= 1) {
            int n = __shfl_up_sync(0xffffffffu, s, o);
            if (lane >= o) s += n;
        }
        if (lane < 8) warpsum[lane] = s;
    }
    __syncthreads();
    int off = inc - v3;
    if (wid > 0) off += warpsum[wid - 1];
    v0 += off; v1 += off; v2 += off; v3 += off;
    if (base + 3 < L) {
        *(int4*)(d + base) = make_int4(v0, v1, v2, v3);
    } else {
        if (base < L) d[base] = v0;
        if (base + 1 < L) d[base + 1] = v1;
        if (base + 2 < L) d[base + 2] = v2;
    }
    if (t == 255) bsums[blockIdx.x] = v3;
}

__global__ void k_scan_sums(int* __restrict__ bsums, int nb) {
    __shared__ int ws[4];
    const int t = threadIdx.x, lane = t & 31, wid = t >> 5;
    int v = (t < nb) ? bsums[t] : 0;
    int inc = v;
#pragma unroll
    for (int o = 1; o < 32; o <<= 1) {
        int n = __shfl_up_sync(0xffffffffu, inc, o);
        if (lane >= o) inc += n;
    }
    if (lane == 31) ws[wid] = inc;
    __syncthreads();
    if (t == 0) {
        int run = 0;
#pragma unroll
        for (int i = 0; i < 4; i++) { int tmp = ws[i]; ws[i] = run; run += tmp; }
    }
    __syncthreads();
    int excl = inc - v + ws[wid];
    if (t < nb) bsums[t] = excl;
}

__global__ void k_scan_add(int* __restrict__ d, int L) {
    const int b = blockIdx.x;
    if (b == 0) return;
    const int add = g_bsums[b];
    const int base = b * 1024 + threadIdx.x * 4;
#pragma unroll
    for (int j = 0; j < 4; j++)
        if (base + j < L) d[base + j] += add;
}

__global__ void k_scatter(const int* __restrict__ rows, const int* __restrict__ cols,
                          const float* __restrict__ vals, int E) {
    int e = blockIdx.x * blockDim.x + threadIdx.x;
    if (e >= E) return;
    int r = rows[e];
    int idx = g_rowptr[r] + atomicAdd(&g_cursor[r], 1);
    g_edges[idx] = make_int2(cols[e], __float_as_int(vals[e]));
}

// ---------------------------------------------------------------------------
// TF32 tensor-core GEMM: C[M,N] = A[M,K] @ B[K,N].
template<int BN, int WARPS_M, int WARPS_N>
__global__ __launch_bounds__(256) void tf32_gemm(
        const float* __restrict__ A, const float* __restrict__ B,
        float* __restrict__ C, int M, int N, int K) {
    constexpr int BM = 128;
    constexpr int BK = 32;
    constexpr int WM = BM / WARPS_M;
    constexpr int WN = BN / WARPS_N;
    constexpr int MFR = WM / 16;
    constexpr int NFR = WN / 8;
    constexpr int ASTRIDE = BK + 4;
    constexpr int BSTRIDE = BN + 8;

    __shared__ uint32_t As[BM][ASTRIDE];
    __shared__ uint32_t Bs[BK][BSTRIDE];

    const int tid  = threadIdx.x;
    const int warp = tid >> 5;
    const int lane = tid & 31;
    const int wm = (warp % WARPS_M) * WM;
    const int wn = (warp / WARPS_M) * WN;
    const int rowBase = blockIdx.y * BM;
    const int colBase = blockIdx.x * BN;

    float acc[MFR][NFR][4];
#pragma unroll
    for (int i = 0; i < MFR; i++)
#pragma unroll
        for (int j = 0; j < NFR; j++)
#pragma unroll
            for (int q = 0; q < 4; q++) acc[i][j][q] = 0.f;

    const int arow = tid >> 1;
    const int acol0 = (tid & 1) * 16;
    const int brow = tid >> 3;
    const int bf40 = tid & 7;

    for (int k0 = 0; k0 < K; k0 += BK) {
        {
            const int gr = rowBase + arow;
            const float* ap = A + (size_t)gr * K + k0 + acol0;
#pragma unroll
            for (int i = 0; i < 4; i++) {
                float4 a = make_float4(0.f, 0.f, 0.f, 0.f);
                if (gr < M) a = *(const float4*)(ap + i * 4);
                const int c = acol0 + i * 4;
                As[arow][c + 0] = f2tf32(a.x);
                As[arow][c + 1] = f2tf32(a.y);
                As[arow][c + 2] = f2tf32(a.z);
                As[arow][c + 3] = f2tf32(a.w);
            }
        }
        {
            const float* bp = B + (size_t)(k0 + brow) * N + colBase;
#pragma unroll
            for (int i = 0; i < BN / 32; i++) {
                const int f4 = bf40 + i * 8;
                float4 b = *(const float4*)(bp + f4 * 4);
                Bs[brow][f4 * 4 + 0] = f2tf32(b.x);
                Bs[brow][f4 * 4 + 1] = f2tf32(b.y);
                Bs[brow][f4 * 4 + 2] = f2tf32(b.z);
                Bs[brow][f4 * 4 + 3] = f2tf32(b.w);
            }
        }
        __syncthreads();

#pragma unroll
        for (int ks = 0; ks < BK / 8; ks++) {
            uint32_t afr[MFR][4];
            uint32_t bfr[NFR][2];
            const int ar = wm + (lane >> 2);
            const int ac = ks * 8 + (lane & 3);
#pragma unroll
            for (int mi = 0; mi < MFR; mi++) {
                afr[mi][0] = As[ar + mi * 16 + 0][ac + 0];
                afr[mi][1] = As[ar + mi * 16 + 8][ac + 0];
                afr[mi][2] = As[ar + mi * 16 + 0][ac + 4];
                afr[mi][3] = As[ar + mi * 16 + 8][ac + 4];
            }
            const int br = ks * 8 + (lane & 3);
            const int bc = wn + (lane >> 2);
#pragma unroll
            for (int ni = 0; ni < NFR; ni++) {
                bfr[ni][0] = Bs[br + 0][bc + ni * 8];
                bfr[ni][1] = Bs[br + 4][bc + ni * 8];
            }
#pragma unroll
            for (int mi = 0; mi < MFR; mi++)
#pragma unroll
                for (int ni = 0; ni < NFR; ni++)
                    mma_tf32(acc[mi][ni], afr[mi], bfr[ni]);
        }
        __syncthreads();
    }

#pragma unroll
    for (int mi = 0; mi < MFR; mi++) {
#pragma unroll
        for (int ni = 0; ni < NFR; ni++) {
            const int r0 = rowBase + wm + mi * 16 + (lane >> 2);
            const int c0 = colBase + wn + ni * 8 + 2 * (lane & 3);
            if (r0 < M)
                *(float2*)(C + (size_t)r0 * N + c0) = make_float2(acc[mi][ni][0], acc[mi][ni][1]);
            if (r0 + 8 < M)
                *(float2*)(C + (size_t)(r0 + 8) * N + c0) = make_float2(acc[mi][ni][2], acc[mi][ni][3]);
        }
    }
}

// ---------------------------------------------------------------------------
// CSR SpMM, F=256, 128-feature chunk per launch (off4 in {0,32}).
// One warp per row, float4 per lane. Fused bias+relu. Streaming stores.
__global__ void spmm_csr_f256(const float* __restrict__ X, const float* __restrict__ bias,
                              float* __restrict__ Y, int off4) {
    const int r = (blockIdx.x * blockDim.x + threadIdx.x) >> 5;
    const int lane = threadIdx.x & 31;
    if (r >= NNODE) return;
    const int start = g_rowptr[r];
    const int end   = g_rowptr[r + 1];
    float4 acc = make_float4(0.f, 0.f, 0.f, 0.f);
    const float4* Xb = (const float4*)X + off4 + lane;
    for (int base = start; base < end; base += 32) {
        const int m = min(32, end - base);
        int2 ev = make_int2(0, 0);
        if (lane < m) ev = g_edges[base + lane];
#pragma unroll 4
        for (int j = 0; j < m; j++) {
            const int   cj = __shfl_sync(0xffffffffu, ev.x, j);
            const float vj = __int_as_float(__shfl_sync(0xffffffffu, ev.y, j));
            float4 xs = __ldg(Xb + (size_t)cj * 64);
            acc.x = fmaf(vj, xs.x, acc.x);
            acc.y = fmaf(vj, xs.y, acc.y);
            acc.z = fmaf(vj, xs.z, acc.z);
            acc.w = fmaf(vj, xs.w, acc.w);
        }
    }
    float4 bb = __ldg((const float4*)bias + off4 + lane);
    acc.x = fmaxf(acc.x + bb.x, 0.f);
    acc.y = fmaxf(acc.y + bb.y, 0.f);
    acc.z = fmaxf(acc.z + bb.z, 0.f);
    acc.w = fmaxf(acc.w + bb.w, 0.f);
    stcs4((float4*)Y + (size_t)r * 64 + off4 + lane, acc);
}

// CSR SpMM F=64 fused with bias + log_softmax. One warp per row, float2/lane.
__global__ void spmm_csr_f64_ls(const float* __restrict__ X, const float* __restrict__ bias,
                                float* __restrict__ out) {
    const int r = (blockIdx.x * blockDim.x + threadIdx.x) >> 5;
    const int lane = threadIdx.x & 31;
    if (r >= NNODE) return;
    const int start = g_rowptr[r];
    const int end   = g_rowptr[r + 1];
    float2 acc = make_float2(0.f, 0.f);
    const float2* Xb = (const float2*)X + lane;
    for (int base = start; base < end; base += 32) {
        const int m = min(32, end - base);
        int2 ev = make_int2(0, 0);
        if (lane < m) ev = g_edges[base + lane];
#pragma unroll 4
        for (int j = 0; j < m; j++) {
            const int   cj = __shfl_sync(0xffffffffu, ev.x, j);
            const float vj = __int_as_float(__shfl_sync(0xffffffffu, ev.y, j));
            float2 xs = __ldg(Xb + (size_t)cj * 32);
            acc.x = fmaf(vj, xs.x, acc.x);
            acc.y = fmaf(vj, xs.y, acc.y);
        }
    }
    float2 bb = __ldg((const float2*)bias + lane);
    float v0 = acc.x + bb.x;
    float v1 = acc.y + bb.y;
    float mx = fmaxf(v0, v1);
#pragma unroll
    for (int o = 16; o; o >>= 1) mx = fmaxf(mx, __shfl_xor_sync(0xffffffffu, mx, o));
    float s = __expf(v0 - mx) + __expf(v1 - mx);
#pragma unroll
    for (int o = 16; o; o >>= 1) s += __shfl_xor_sync(0xffffffffu, s, o);
    float lse = mx + __logf(s);
    float2* w = (float2*)out + (size_t)r * 32 + lane;
    *w = make_float2(v0 - lse, v1 - lse);
}

// ---------------------------------------------------------------------------
extern "C" void kernel_launch(void* const* d_in, const int* in_sizes, int n_in,
                              void* d_out, int out_size) {
    const float* x    = (const float*)d_in[0];
    const int*   erow = (const int*)d_in[1];
    const int*   ecol = (const int*)d_in[2];
    const float* eval_ = (const float*)d_in[3];
    const float* W1   = (const float*)d_in[4];
    const float* b1   = (const float*)d_in[5];
    const float* W2   = (const float*)d_in[6];
    const float* b2   = (const float*)d_in[7];
    float* out = (float*)d_out;

    const int E = in_sizes[1];
    const int M = in_sizes[0] / NF;  // 100000

    float *xw1, *h, *hw2;
    int *rowptr, *bsums;
    cudaGetSymbolAddress((void**)&xw1, g_xw1);
    cudaGetSymbolAddress((void**)&h, g_h);
    cudaGetSymbolAddress((void**)&hw2, g_hw2);
    cudaGetSymbolAddress((void**)&rowptr, g_rowptr);
    cudaGetSymbolAddress((void**)&bsums, g_bsums);

    const int L = NNODE + 1;
    const int nscan = (L + 1023) / 1024;  // 98

    // --- CSR build ---
    k_zero_csr<<<(NNODE + 256) / 256, 256>>>();
    k_hist<<<(E + 255) / 256, 256>>>(erow, E);
    k_scan_block<<<nscan, 256>>>(rowptr, L, bsums);
    k_scan_sums<<<1, 128>>>(bsums, nscan);
    k_scan_add<<<nscan, 256>>>(rowptr, L);
    k_scatter<<<(E + 255) / 256, 256>>>(erow, ecol, eval_, E);

    // layer 1: XW1 = x @ W1  (tf32 tensor cores, 128x128 tile)
    tf32_gemm<128, 2, 4><<<dim3(NH / 128, (M + 127) / 128), 256>>>(x, W1, xw1, M, NH, NF);

    // spmm1 (CSR gather, 2 feature chunks for L2 residency) + fused bias/relu
    {
        int blocks = (NNODE * 32 + 255) / 256;
        spmm_csr_f256<<<blocks, 256>>>(xw1, b1, h, 0);
        spmm_csr_f256<<<blocks, 256>>>(xw1, b1, h, 32);
    }

    // layer 2: HW2 = h @ W2  (tf32 tensor cores, 128x64 tile)
    tf32_gemm<64, 4, 2><<<dim3(NC / 64, (M + 127) / 128), 256>>>(h, W2, hw2, M, NC, NH);

    // spmm2 (CSR gather) + fused bias + log_softmax
    {
        int blocks = (NNODE * 32 + 255) / 256;
        spmm_csr_f64_ls<<<blocks, 256>>>(hw2, b2, out);
    }
}

// round 5
// speedup vs baseline: 3.4705x; 1.2495x over previous
#include <cuda_runtime.h>
#include <cuda_fp16.h>
#include <cstdint>

// Problem constants (shapes fixed by the reference)
constexpr int NF = 512;   // input features
constexpr int NH = 256;   // hidden
constexpr int NC = 64;    // classes
constexpr int NNODE = 100000;
constexpr int EMAX = 3200000;

// Scratch (allocation-free rule: __device__ globals)
__device__ __half g_xw1[(size_t)NNODE * NH];  // x @ W1 (fp16)
__device__ __half g_h[(size_t)NNODE * NH];    // spmm1 out / h (fp16)
__device__ float  g_hw2[(size_t)NNODE * NC];  // h @ W2
__device__ int    g_rowptr[NNODE + 1];
__device__ int    g_cursor[NNODE];
__device__ int2   g_edges[EMAX];              // (col, val-bits) sorted by row
__device__ int    g_bsums[128];

// ---------------------------------------------------------------------------
__device__ __forceinline__ uint32_t f2tf32(float f) {
    uint32_t r;
    asm("cvt.rna.tf32.f32 %0, %1;" : "=r"(r) : "f"(f));
    return r;
}

__device__ __forceinline__ void mma_tf32(float c[4], const uint32_t a[4], const uint32_t b[2]) {
    asm volatile(
        "mma.sync.aligned.m16n8k8.row.col.f32.tf32.tf32.f32 "
        "{%0,%1,%2,%3}, {%4,%5,%6,%7}, {%8,%9}, {%0,%1,%2,%3};"
        : "+f"(c[0]), "+f"(c[1]), "+f"(c[2]), "+f"(c[3])
        : "r"(a[0]), "r"(a[1]), "r"(a[2]), "r"(a[3]), "r"(b[0]), "r"(b[1]));
}

__device__ __forceinline__ void stcs_u4(uint4* p, uint4 v) {
    asm volatile("st.global.cs.v4.u32 [%0], {%1,%2,%3,%4};"
                 :: "l"(p), "r"(v.x), "r"(v.y), "r"(v.z), "r"(v.w) : "memory");
}

// ---------------------------------------------------------------------------
// CSR build
__global__ void k_zero_csr() {
    int i = blockIdx.x * blockDim.x + threadIdx.x;
    if (i <= NNODE) g_rowptr[i] = 0;
    if (i < NNODE) g_cursor[i] = 0;
}

__global__ void k_hist(const int* __restrict__ rows, int E) {
    int e = blockIdx.x * blockDim.x + threadIdx.x;
    if (e < E) atomicAdd(&g_rowptr[rows[e] + 1], 1);
}

// inclusive block scan: 1024 elements per block (256 threads x 4)
__global__ void k_scan_block(int* __restrict__ d, int L, int* __restrict__ bsums) {
    __shared__ int warpsum[8];
    const int t = threadIdx.x, lane = t & 31, wid = t >> 5;
    const int base = blockIdx.x * 1024 + t * 4;
    int v0 = 0, v1 = 0, v2 = 0, v3 = 0;
    if (base + 3 < L) {
        int4 x = *(const int4*)(d + base);
        v0 = x.x; v1 = x.y; v2 = x.z; v3 = x.w;
    } else {
        if (base < L) v0 = d[base];
        if (base + 1 < L) v1 = d[base + 1];
        if (base + 2 < L) v2 = d[base + 2];
    }
    v1 += v0; v2 += v1; v3 += v2;
    int inc = v3;
#pragma unroll
    for (int o = 1; o < 32; o <<= 1) {
        int n = __shfl_up_sync(0xffffffffu, inc, o);
        if (lane >= o) inc += n;
    }
    if (lane == 31) warpsum[wid] = inc;
    __syncthreads();
    if (wid == 0) {
        int s = (lane < 8) ? warpsum[lane] : 0;
#pragma unroll
        for (int o = 1; o < 8; o <<= 1) {
            int n = __shfl_up_sync(0xffffffffu, s, o);
            if (lane >= o) s += n;
        }
        if (lane < 8) warpsum[lane] = s;
    }
    __syncthreads();
    int off = inc - v3;
    if (wid > 0) off += warpsum[wid - 1];
    v0 += off; v1 += off; v2 += off; v3 += off;
    if (base + 3 < L) {
        *(int4*)(d + base) = make_int4(v0, v1, v2, v3);
    } else {
        if (base < L) d[base] = v0;
        if (base + 1 < L) d[base + 1] = v1;
        if (base + 2 < L) d[base + 2] = v2;
    }
    if (t == 255) bsums[blockIdx.x] = v3;
}

__global__ void k_scan_sums(int* __restrict__ bsums, int nb) {
    __shared__ int ws[4];
    const int t = threadIdx.x, lane = t & 31, wid = t >> 5;
    int v = (t < nb) ? bsums[t] : 0;
    int inc = v;
#pragma unroll
    for (int o = 1; o < 32; o <<= 1) {
        int n = __shfl_up_sync(0xffffffffu, inc, o);
        if (lane >= o) inc += n;
    }
    if (lane == 31) ws[wid] = inc;
    __syncthreads();
    if (t == 0) {
        int run = 0;
#pragma unroll
        for (int i = 0; i < 4; i++) { int tmp = ws[i]; ws[i] = run; run += tmp; }
    }
    __syncthreads();
    int excl = inc - v + ws[wid];
    if (t < nb) bsums[t] = excl;
}

__global__ void k_scan_add(int* __restrict__ d, int L) {
    const int b = blockIdx.x;
    if (b == 0) return;
    const int add = g_bsums[b];
    const int base = b * 1024 + threadIdx.x * 4;
#pragma unroll
    for (int j = 0; j < 4; j++)
        if (base + j < L) d[base + j] += add;
}

__global__ void k_scatter(const int* __restrict__ rows, const int* __restrict__ cols,
                          const float* __restrict__ vals, int E) {
    int e = blockIdx.x * blockDim.x + threadIdx.x;
    if (e >= E) return;
    int r = rows[e];
    int idx = g_rowptr[r] + atomicAdd(&g_cursor[r], 1);
    g_edges[idx] = make_int2(cols[e], __float_as_int(vals[e]));
}

// ---------------------------------------------------------------------------
// TF32 GEMM, fp32 A, fp16 C: C[M,N] = A[M,K] @ B[K,N].  BM=128, BK=32, 8 warps.
template<int BN, int WARPS_M, int WARPS_N>
__global__ __launch_bounds__(256) void tf32_gemm_f16out(
        const float* __restrict__ A, const float* __restrict__ B,
        __half* __restrict__ C, int M, int N, int K) {
    constexpr int BM = 128;
    constexpr int BK = 32;
    constexpr int WM = BM / WARPS_M;
    constexpr int WN = BN / WARPS_N;
    constexpr int MFR = WM / 16;
    constexpr int NFR = WN / 8;
    constexpr int ASTRIDE = BK + 4;
    constexpr int BSTRIDE = BN + 8;

    __shared__ uint32_t As[BM][ASTRIDE];
    __shared__ uint32_t Bs[BK][BSTRIDE];

    const int tid  = threadIdx.x;
    const int warp = tid >> 5;
    const int lane = tid & 31;
    const int wm = (warp % WARPS_M) * WM;
    const int wn = (warp / WARPS_M) * WN;
    const int rowBase = blockIdx.y * BM;
    const int colBase = blockIdx.x * BN;

    float acc[MFR][NFR][4];
#pragma unroll
    for (int i = 0; i < MFR; i++)
#pragma unroll
        for (int j = 0; j < NFR; j++)
#pragma unroll
            for (int q = 0; q < 4; q++) acc[i][j][q] = 0.f;

    const int arow = tid >> 1;
    const int acol0 = (tid & 1) * 16;
    const int brow = tid >> 3;
    const int bf40 = tid & 7;

    for (int k0 = 0; k0 < K; k0 += BK) {
        {
            const int gr = rowBase + arow;
            const float* ap = A + (size_t)gr * K + k0 + acol0;
#pragma unroll
            for (int i = 0; i < 4; i++) {
                float4 a = make_float4(0.f, 0.f, 0.f, 0.f);
                if (gr < M) a = *(const float4*)(ap + i * 4);
                const int c = acol0 + i * 4;
                As[arow][c + 0] = f2tf32(a.x);
                As[arow][c + 1] = f2tf32(a.y);
                As[arow][c + 2] = f2tf32(a.z);
                As[arow][c + 3] = f2tf32(a.w);
            }
        }
        {
            const float* bp = B + (size_t)(k0 + brow) * N + colBase;
#pragma unroll
            for (int i = 0; i < BN / 32; i++) {
                const int f4 = bf40 + i * 8;
                float4 b = *(const float4*)(bp + f4 * 4);
                Bs[brow][f4 * 4 + 0] = f2tf32(b.x);
                Bs[brow][f4 * 4 + 1] = f2tf32(b.y);
                Bs[brow][f4 * 4 + 2] = f2tf32(b.z);
                Bs[brow][f4 * 4 + 3] = f2tf32(b.w);
            }
        }
        __syncthreads();

#pragma unroll
        for (int ks = 0; ks < BK / 8; ks++) {
            uint32_t afr[MFR][4];
            uint32_t bfr[NFR][2];
            const int ar = wm + (lane >> 2);
            const int ac = ks * 8 + (lane & 3);
#pragma unroll
            for (int mi = 0; mi < MFR; mi++) {
                afr[mi][0] = As[ar + mi * 16 + 0][ac + 0];
                afr[mi][1] = As[ar + mi * 16 + 8][ac + 0];
                afr[mi][2] = As[ar + mi * 16 + 0][ac + 4];
                afr[mi][3] = As[ar + mi * 16 + 8][ac + 4];
            }
            const int br = ks * 8 + (lane & 3);
            const int bc = wn + (lane >> 2);
#pragma unroll
            for (int ni = 0; ni < NFR; ni++) {
                bfr[ni][0] = Bs[br + 0][bc + ni * 8];
                bfr[ni][1] = Bs[br + 4][bc + ni * 8];
            }
#pragma unroll
            for (int mi = 0; mi < MFR; mi++)
#pragma unroll
                for (int ni = 0; ni < NFR; ni++)
                    mma_tf32(acc[mi][ni], afr[mi], bfr[ni]);
        }
        __syncthreads();
    }

#pragma unroll
    for (int mi = 0; mi < MFR; mi++) {
#pragma unroll
        for (int ni = 0; ni < NFR; ni++) {
            const int r0 = rowBase + wm + mi * 16 + (lane >> 2);
            const int c0 = colBase + wn + ni * 8 + 2 * (lane & 3);
            if (r0 < M)
                *(__half2*)(C + (size_t)r0 * N + c0) =
                    __floats2half2_rn(acc[mi][ni][0], acc[mi][ni][1]);
            if (r0 + 8 < M)
                *(__half2*)(C + (size_t)(r0 + 8) * N + c0) =
                    __floats2half2_rn(acc[mi][ni][2], acc[mi][ni][3]);
        }
    }
}

// TF32 GEMM, fp16 A, fp32 C (fp16->tf32 is exact).
template<int BN, int WARPS_M, int WARPS_N>
__global__ __launch_bounds__(256) void tf32_gemm_f16in(
        const __half* __restrict__ A, const float* __restrict__ B,
        float* __restrict__ C, int M, int N, int K) {
    constexpr int BM = 128;
    constexpr int BK = 32;
    constexpr int WM = BM / WARPS_M;
    constexpr int WN = BN / WARPS_N;
    constexpr int MFR = WM / 16;
    constexpr int NFR = WN / 8;
    constexpr int ASTRIDE = BK + 4;
    constexpr int BSTRIDE = BN + 8;

    __shared__ uint32_t As[BM][ASTRIDE];
    __shared__ uint32_t Bs[BK][BSTRIDE];

    const int tid  = threadIdx.x;
    const int warp = tid >> 5;
    const int lane = tid & 31;
    const int wm = (warp % WARPS_M) * WM;
    const int wn = (warp / WARPS_M) * WN;
    const int rowBase = blockIdx.y * BM;
    const int colBase = blockIdx.x * BN;

    float acc[MFR][NFR][4];
#pragma unroll
    for (int i = 0; i < MFR; i++)
#pragma unroll
        for (int j = 0; j < NFR; j++)
#pragma unroll
            for (int q = 0; q < 4; q++) acc[i][j][q] = 0.f;

    const int arow = tid >> 1;
    const int acol0 = (tid & 1) * 16;
    const int brow = tid >> 3;
    const int bf40 = tid & 7;

    for (int k0 = 0; k0 < K; k0 += BK) {
        {
            const int gr = rowBase + arow;
            const __half* ap = A + (size_t)gr * K + k0 + acol0;
            uint4 q0 = make_uint4(0, 0, 0, 0), q1 = make_uint4(0, 0, 0, 0);
            if (gr < M) {
                q0 = *(const uint4*)ap;
                q1 = *(const uint4*)(ap + 8);
            }
            const __half2* hp0 = (const __half2*)&q0;
            const __half2* hp1 = (const __half2*)&q1;
#pragma unroll
            for (int i = 0; i < 4; i++) {
                float2 f0 = __half22float2(hp0[i]);
                float2 f1 = __half22float2(hp1[i]);
                As[arow][acol0 + i * 2 + 0] = f2tf32(f0.x);
                As[arow][acol0 + i * 2 + 1] = f2tf32(f0.y);
                As[arow][acol0 + 8 + i * 2 + 0] = f2tf32(f1.x);
                As[arow][acol0 + 8 + i * 2 + 1] = f2tf32(f1.y);
            }
        }
        {
            const float* bp = B + (size_t)(k0 + brow) * N + colBase;
#pragma unroll
            for (int i = 0; i < BN / 32; i++) {
                const int f4 = bf40 + i * 8;
                float4 b = *(const float4*)(bp + f4 * 4);
                Bs[brow][f4 * 4 + 0] = f2tf32(b.x);
                Bs[brow][f4 * 4 + 1] = f2tf32(b.y);
                Bs[brow][f4 * 4 + 2] = f2tf32(b.z);
                Bs[brow][f4 * 4 + 3] = f2tf32(b.w);
            }
        }
        __syncthreads();

#pragma unroll
        for (int ks = 0; ks < BK / 8; ks++) {
            uint32_t afr[MFR][4];
            uint32_t bfr[NFR][2];
            const int ar = wm + (lane >> 2);
            const int ac = ks * 8 + (lane & 3);
#pragma unroll
            for (int mi = 0; mi < MFR; mi++) {
                afr[mi][0] = As[ar + mi * 16 + 0][ac + 0];
                afr[mi][1] = As[ar + mi * 16 + 8][ac + 0];
                afr[mi][2] = As[ar + mi * 16 + 0][ac + 4];
                afr[mi][3] = As[ar + mi * 16 + 8][ac + 4];
            }
            const int br = ks * 8 + (lane & 3);
            const int bc = wn + (lane >> 2);
#pragma unroll
            for (int ni = 0; ni < NFR; ni++) {
                bfr[ni][0] = Bs[br + 0][bc + ni * 8];
                bfr[ni][1] = Bs[br + 4][bc + ni * 8];
            }
#pragma unroll
            for (int mi = 0; mi < MFR; mi++)
#pragma unroll
                for (int ni = 0; ni < NFR; ni++)
                    mma_tf32(acc[mi][ni], afr[mi], bfr[ni]);
        }
        __syncthreads();
    }

#pragma unroll
    for (int mi = 0; mi < MFR; mi++) {
#pragma unroll
        for (int ni = 0; ni < NFR; ni++) {
            const int r0 = rowBase + wm + mi * 16 + (lane >> 2);
            const int c0 = colBase + wn + ni * 8 + 2 * (lane & 3);
            if (r0 < M)
                *(float2*)(C + (size_t)r0 * N + c0) = make_float2(acc[mi][ni][0], acc[mi][ni][1]);
            if (r0 + 8 < M)
                *(float2*)(C + (size_t)(r0 + 8) * N + c0) = make_float2(acc[mi][ni][2], acc[mi][ni][3]);
        }
    }
}

// ---------------------------------------------------------------------------
// CSR SpMM, F=256, fp16 source, single pass. One warp per row; each lane owns
// 8 halfs (one uint4). Fused bias+relu; fp16 streaming output.
__global__ void spmm_csr_f256h(const __half* __restrict__ X, const float* __restrict__ bias,
                               __half* __restrict__ Y) {
    const int r = (blockIdx.x * blockDim.x + threadIdx.x) >> 5;
    const int lane = threadIdx.x & 31;
    if (r >= NNODE) return;
    const int start = g_rowptr[r];
    const int end   = g_rowptr[r + 1];
    float acc[8];
#pragma unroll
    for (int i = 0; i < 8; i++) acc[i] = 0.f;
    const uint4* Xb = (const uint4*)X + lane;  // row stride = 32 uint4
    for (int base = start; base < end; base += 32) {
        const int m = min(32, end - base);
        int2 ev = make_int2(0, 0);
        if (lane < m) ev = g_edges[base + lane];
#pragma unroll 4
        for (int j = 0; j < m; j++) {
            const int   cj = __shfl_sync(0xffffffffu, ev.x, j);
            const float vj = __int_as_float(__shfl_sync(0xffffffffu, ev.y, j));
            uint4 q = __ldg(Xb + (size_t)cj * 32);
            const __half2* hp = (const __half2*)&q;
#pragma unroll
            for (int i = 0; i < 4; i++) {
                float2 f = __half22float2(hp[i]);
                acc[i * 2 + 0] = fmaf(vj, f.x, acc[i * 2 + 0]);
                acc[i * 2 + 1] = fmaf(vj, f.y, acc[i * 2 + 1]);
            }
        }
    }
    float4 b0 = __ldg((const float4*)bias + lane * 2);
    float4 b1 = __ldg((const float4*)bias + lane * 2 + 1);
    float bb[8] = {b0.x, b0.y, b0.z, b0.w, b1.x, b1.y, b1.z, b1.w};
    __half2 o[4];
#pragma unroll
    for (int i = 0; i < 4; i++)
        o[i] = __floats2half2_rn(fmaxf(acc[i * 2] + bb[i * 2], 0.f),
                                 fmaxf(acc[i * 2 + 1] + bb[i * 2 + 1], 0.f));
    uint4 ov = *(const uint4*)o;
    stcs_u4((uint4*)Y + (size_t)r * 32 + lane, ov);
}

// CSR SpMM F=64 fused with bias + log_softmax. One warp per row, float2/lane.
__global__ void spmm_csr_f64_ls(const float* __restrict__ X, const float* __restrict__ bias,
                                float* __restrict__ out) {
    const int r = (blockIdx.x * blockDim.x + threadIdx.x) >> 5;
    const int lane = threadIdx.x & 31;
    if (r >= NNODE) return;
    const int start = g_rowptr[r];
    const int end   = g_rowptr[r + 1];
    float2 acc = make_float2(0.f, 0.f);
    const float2* Xb = (const float2*)X + lane;
    for (int base = start; base < end; base += 32) {
        const int m = min(32, end - base);
        int2 ev = make_int2(0, 0);
        if (lane < m) ev = g_edges[base + lane];
#pragma unroll 4
        for (int j = 0; j < m; j++) {
            const int   cj = __shfl_sync(0xffffffffu, ev.x, j);
            const float vj = __int_as_float(__shfl_sync(0xffffffffu, ev.y, j));
            float2 xs = __ldg(Xb + (size_t)cj * 32);
            acc.x = fmaf(vj, xs.x, acc.x);
            acc.y = fmaf(vj, xs.y, acc.y);
        }
    }
    float2 bb = __ldg((const float2*)bias + lane);
    float v0 = acc.x + bb.x;
    float v1 = acc.y + bb.y;
    float mx = fmaxf(v0, v1);
#pragma unroll
    for (int o = 16; o; o >>= 1) mx = fmaxf(mx, __shfl_xor_sync(0xffffffffu, mx, o));
    float s = __expf(v0 - mx) + __expf(v1 - mx);
#pragma unroll
    for (int o = 16; o; o >>= 1) s += __shfl_xor_sync(0xffffffffu, s, o);
    float lse = mx + __logf(s);
    float2* w = (float2*)out + (size_t)r * 32 + lane;
    *w = make_float2(v0 - lse, v1 - lse);
}

// ---------------------------------------------------------------------------
extern "C" void kernel_launch(void* const* d_in, const int* in_sizes, int n_in,
                              void* d_out, int out_size) {
    const float* x    = (const float*)d_in[0];
    const int*   erow = (const int*)d_in[1];
    const int*   ecol = (const int*)d_in[2];
    const float* eval_ = (const float*)d_in[3];
    const float* W1   = (const float*)d_in[4];
    const float* b1   = (const float*)d_in[5];
    const float* W2   = (const float*)d_in[6];
    const float* b2   = (const float*)d_in[7];
    float* out = (float*)d_out;

    const int E = in_sizes[1];
    const int M = in_sizes[0] / NF;  // 100000

    __half *xw1, *h;
    float *hw2;
    int *rowptr, *bsums;
    cudaGetSymbolAddress((void**)&xw1, g_xw1);
    cudaGetSymbolAddress((void**)&h, g_h);
    cudaGetSymbolAddress((void**)&hw2, g_hw2);
    cudaGetSymbolAddress((void**)&rowptr, g_rowptr);
    cudaGetSymbolAddress((void**)&bsums, g_bsums);

    const int L = NNODE + 1;
    const int nscan = (L + 1023) / 1024;  // 98

    // --- CSR build ---
    k_zero_csr<<<(NNODE + 256) / 256, 256>>>();
    k_hist<<<(E + 255) / 256, 256>>>(erow, E);
    k_scan_block<<<nscan, 256>>>(rowptr, L, bsums);
    k_scan_sums<<<1, 128>>>(bsums, nscan);
    k_scan_add<<<nscan, 256>>>(rowptr, L);
    k_scatter<<<(E + 255) / 256, 256>>>(erow, ecol, eval_, E);

    // layer 1: XW1 = x @ W1  (tf32 tensor cores, fp16 output)
    tf32_gemm_f16out<128, 2, 4><<<dim3(NH / 128, (M + 127) / 128), 256>>>(x, W1, xw1, M, NH, NF);

    // spmm1 (CSR gather, fp16, single pass, source L2-resident) + fused bias/relu
    {
        int blocks = (NNODE * 32 + 255) / 256;
        spmm_csr_f256h<<<blocks, 256>>>(xw1, b1, h);
    }

    // layer 2: HW2 = h @ W2  (tf32 tensor cores, fp16 input)
    tf32_gemm_f16in<64, 4, 2><<<dim3(NC / 64, (M + 127) / 128), 256>>>(h, W2, hw2, M, NC, NH);

    // spmm2 (CSR gather) + fused bias + log_softmax
    {
        int blocks = (NNODE * 32 + 255) / 256;
        spmm_csr_f64_ls<<<blocks, 256>>>(hw2, b2, out);
    }
}

// round 6
// speedup vs baseline: 3.7807x; 1.0894x over previous
#include <cuda_runtime.h>
#include <cuda_fp16.h>
#include <cstdint>

// Problem constants (shapes fixed by the reference)
constexpr int NF = 512;   // input features
constexpr int NH = 256;   // hidden
constexpr int NC = 64;    // classes
constexpr int NNODE = 100000;
constexpr int EMAX = 3200000;

// Scratch (allocation-free rule: __device__ globals)
__device__ __half g_xw1[(size_t)NNODE * NH];  // x @ W1 (fp16)
__device__ __half g_h[(size_t)NNODE * NH];    // spmm1 out / h (fp16)
__device__ __half g_hw2[(size_t)NNODE * NC];  // h @ W2 (fp16)
__device__ int    g_rowptr[NNODE + 1];
__device__ int    g_cursor[NNODE];
__device__ int2   g_edges[EMAX];              // (col, val-bits) sorted by row
__device__ int    g_bsums[128];

// ---------------------------------------------------------------------------
__device__ __forceinline__ void mma_f16(float c[4], const uint32_t a[4], const uint32_t b[2]) {
    asm volatile(
        "mma.sync.aligned.m16n8k16.row.col.f32.f16.f16.f32 "
        "{%0,%1,%2,%3}, {%4,%5,%6,%7}, {%8,%9}, {%0,%1,%2,%3};"
        : "+f"(c[0]), "+f"(c[1]), "+f"(c[2]), "+f"(c[3])
        : "r"(a[0]), "r"(a[1]), "r"(a[2]), "r"(a[3]), "r"(b[0]), "r"(b[1]));
}

__device__ __forceinline__ void stcs_u4(uint4* p, uint4 v) {
    asm volatile("st.global.cs.v4.u32 [%0], {%1,%2,%3,%4};"
                 :: "l"(p), "r"(v.x), "r"(v.y), "r"(v.z), "r"(v.w) : "memory");
}

// ---------------------------------------------------------------------------
// CSR build
__global__ void k_zero_csr() {
    int i = blockIdx.x * blockDim.x + threadIdx.x;
    if (i <= NNODE) g_rowptr[i] = 0;
    if (i < NNODE) g_cursor[i] = 0;
}

__global__ void k_hist(const int* __restrict__ rows, int E) {
    int e = blockIdx.x * blockDim.x + threadIdx.x;
    if (e < E) atomicAdd(&g_rowptr[rows[e] + 1], 1);
}

// inclusive block scan: 1024 elements per block (256 threads x 4)
__global__ void k_scan_block(int* __restrict__ d, int L, int* __restrict__ bsums) {
    __shared__ int warpsum[8];
    const int t = threadIdx.x, lane = t & 31, wid = t >> 5;
    const int base = blockIdx.x * 1024 + t * 4;
    int v0 = 0, v1 = 0, v2 = 0, v3 = 0;
    if (base + 3 < L) {
        int4 x = *(const int4*)(d + base);
        v0 = x.x; v1 = x.y; v2 = x.z; v3 = x.w;
    } else {
        if (base < L) v0 = d[base];
        if (base + 1 < L) v1 = d[base + 1];
        if (base + 2 < L) v2 = d[base + 2];
    }
    v1 += v0; v2 += v1; v3 += v2;
    int inc = v3;
#pragma unroll
    for (int o = 1; o < 32; o <<= 1) {
        int n = __shfl_up_sync(0xffffffffu, inc, o);
        if (lane >= o) inc += n;
    }
    if (lane == 31) warpsum[wid] = inc;
    __syncthreads();
    if (wid == 0) {
        int s = (lane < 8) ? warpsum[lane] : 0;
#pragma unroll
        for (int o = 1; o < 8; o <<= 1) {
            int n = __shfl_up_sync(0xffffffffu, s, o);
            if (lane >= o) s += n;
        }
        if (lane < 8) warpsum[lane] = s;
    }
    __syncthreads();
    int off = inc - v3;
    if (wid > 0) off += warpsum[wid - 1];
    v0 += off; v1 += off; v2 += off; v3 += off;
    if (base + 3 < L) {
        *(int4*)(d + base) = make_int4(v0, v1, v2, v3);
    } else {
        if (base < L) d[base] = v0;
        if (base + 1 < L) d[base + 1] = v1;
        if (base + 2 < L) d[base + 2] = v2;
    }
    if (t == 255) bsums[blockIdx.x] = v3;
}

__global__ void k_scan_sums(int* __restrict__ bsums, int nb) {
    __shared__ int ws[4];
    const int t = threadIdx.x, lane = t & 31, wid = t >> 5;
    int v = (t < nb) ? bsums[t] : 0;
    int inc = v;
#pragma unroll
    for (int o = 1; o < 32; o <<= 1) {
        int n = __shfl_up_sync(0xffffffffu, inc, o);
        if (lane >= o) inc += n;
    }
    if (lane == 31) ws[wid] = inc;
    __syncthreads();
    if (t == 0) {
        int run = 0;
#pragma unroll
        for (int i = 0; i < 4; i++) { int tmp = ws[i]; ws[i] = run; run += tmp; }
    }
    __syncthreads();
    int excl = inc - v + ws[wid];
    if (t < nb) bsums[t] = excl;
}

__global__ void k_scan_add(int* __restrict__ d, int L) {
    const int b = blockIdx.x;
    if (b == 0) return;
    const int add = g_bsums[b];
    const int base = b * 1024 + threadIdx.x * 4;
#pragma unroll
    for (int j = 0; j < 4; j++)
        if (base + j < L) d[base + j] += add;
}

__global__ void k_scatter(const int* __restrict__ rows, const int* __restrict__ cols,
                          const float* __restrict__ vals, int E) {
    int e = blockIdx.x * blockDim.x + threadIdx.x;
    if (e >= E) return;
    int r = rows[e];
    int idx = g_rowptr[r] + atomicAdd(&g_cursor[r], 1);
    g_edges[idx] = make_int2(cols[e], __float_as_int(vals[e]));
}

// ---------------------------------------------------------------------------
// FP16 tensor-core GEMM (m16n8k16, fp32 accum): C = A @ B.
// A fp32 [M,K] row-major (converted on smem store), B fp32 [K,N], C fp16.
// BM=128, BK=32, 256 threads, warps WARPS_M x WARPS_N.
// As_pack: half2 per 2 consecutive k; stride 20 words -> conflict-free frags.
// Bs_pack[k2][n] (k-pairs), stride BN+8 -> conflict-free frags.
template<int BN, int WARPS_M, int WARPS_N>
__global__ __launch_bounds__(256) void f16_gemm_f32in(
        const float* __restrict__ A, const float* __restrict__ B,
        __half* __restrict__ C, int M, int N, int K) {
    constexpr int BM = 128;
    constexpr int BK = 32;
    constexpr int WM = BM / WARPS_M;
    constexpr int WN = BN / WARPS_N;
    constexpr int MFR = WM / 16;
    constexpr int NFR = WN / 8;
    constexpr int AS2 = 20;       // half2 stride per row (16 data + 4 pad)
    constexpr int BS2 = BN + 8;   // half2 stride per k2 row

    __shared__ __align__(16) __half2 As[BM][AS2];
    __shared__ __align__(16) __half2 Bs[BK / 2][BS2];

    const int tid  = threadIdx.x;
    const int warp = tid >> 5;
    const int lane = tid & 31;
    const int wm = (warp % WARPS_M) * WM;
    const int wn = (warp / WARPS_M) * WN;
    const int rowBase = blockIdx.y * BM;
    const int colBase = blockIdx.x * BN;

    float acc[MFR][NFR][4];
#pragma unroll
    for (int i = 0; i < MFR; i++)
#pragma unroll
        for (int j = 0; j < NFR; j++)
#pragma unroll
            for (int q = 0; q < 4; q++) acc[i][j][q] = 0.f;

    // A: 128 rows x 32 cols fp32; 2 threads/row, 16 floats each
    const int arow = tid >> 1;
    const int acol0 = (tid & 1) * 16;
    // B: 32 rows x BN cols fp32; 8 threads/row, BN/32 float4 each
    const int brow = tid >> 3;
    const int bf40 = tid & 7;

    for (int k0 = 0; k0 < K; k0 += BK) {
        // --- A tile -> half2 packed ---
        {
            const int gr = rowBase + arow;
            const float* ap = A + (size_t)gr * K + k0 + acol0;
            __half2 h[8];
#pragma unroll
            for (int i = 0; i < 4; i++) {
                float4 a = make_float4(0.f, 0.f, 0.f, 0.f);
                if (gr < M) a = *(const float4*)(ap + i * 4);
                h[i * 2 + 0] = __floats2half2_rn(a.x, a.y);
                h[i * 2 + 1] = __floats2half2_rn(a.z, a.w);
            }
            *(uint4*)&As[arow][acol0 / 2 + 0] = *(const uint4*)&h[0];
            *(uint4*)&As[arow][acol0 / 2 + 4] = *(const uint4*)&h[4];
        }
        // --- B tile -> half scattered (transpose k into half2 lanes) ---
        {
            const float* bp = B + (size_t)(k0 + brow) * N + colBase;
            __half* bsh = (__half*)&Bs[brow >> 1][0];
            const int hsel = brow & 1;
#pragma unroll
            for (int i = 0; i < BN / 32; i++) {
                const int n = (bf40 + i * 8) * 4;
                float4 b = *(const float4*)(bp + n);
                bsh[(n + 0) * 2 + hsel] = __float2half_rn(b.x);
                bsh[(n + 1) * 2 + hsel] = __float2half_rn(b.y);
                bsh[(n + 2) * 2 + hsel] = __float2half_rn(b.z);
                bsh[(n + 3) * 2 + hsel] = __float2half_rn(b.w);
            }
        }
        __syncthreads();

#pragma unroll
        for (int ks = 0; ks < BK / 16; ks++) {
            uint32_t afr[MFR][4];
            uint32_t bfr[NFR][2];
            const int ar = wm + (lane >> 2);
            const int kb = ks * 8 + (lane & 3);
#pragma unroll
            for (int mi = 0; mi < MFR; mi++) {
                afr[mi][0] = *(const uint32_t*)&As[ar + mi * 16 + 0][kb + 0];
                afr[mi][1] = *(const uint32_t*)&As[ar + mi * 16 + 8][kb + 0];
                afr[mi][2] = *(const uint32_t*)&As[ar + mi * 16 + 0][kb + 4];
                afr[mi][3] = *(const uint32_t*)&As[ar + mi * 16 + 8][kb + 4];
            }
            const int bc = wn + (lane >> 2);
#pragma unroll
            for (int ni = 0; ni < NFR; ni++) {
                bfr[ni][0] = *(const uint32_t*)&Bs[kb + 0][bc + ni * 8];
                bfr[ni][1] = *(const uint32_t*)&Bs[kb + 4][bc + ni * 8];
            }
#pragma unroll
            for (int mi = 0; mi < MFR; mi++)
#pragma unroll
                for (int ni = 0; ni < NFR; ni++)
                    mma_f16(acc[mi][ni], afr[mi], bfr[ni]);
        }
        __syncthreads();
    }

#pragma unroll
    for (int mi = 0; mi < MFR; mi++) {
#pragma unroll
        for (int ni = 0; ni < NFR; ni++) {
            const int r0 = rowBase + wm + mi * 16 + (lane >> 2);
            const int c0 = colBase + wn + ni * 8 + 2 * (lane & 3);
            if (r0 < M)
                *(__half2*)(C + (size_t)r0 * N + c0) =
                    __floats2half2_rn(acc[mi][ni][0], acc[mi][ni][1]);
            if (r0 + 8 < M)
                *(__half2*)(C + (size_t)(r0 + 8) * N + c0) =
                    __floats2half2_rn(acc[mi][ni][2], acc[mi][ni][3]);
        }
    }
}

// Same GEMM but A is fp16 (direct copy, no conversion).
template<int BN, int WARPS_M, int WARPS_N>
__global__ __launch_bounds__(256) void f16_gemm_f16in(
        const __half* __restrict__ A, const float* __restrict__ B,
        __half* __restrict__ C, int M, int N, int K) {
    constexpr int BM = 128;
    constexpr int BK = 32;
    constexpr int WM = BM / WARPS_M;
    constexpr int WN = BN / WARPS_N;
    constexpr int MFR = WM / 16;
    constexpr int NFR = WN / 8;
    constexpr int AS2 = 20;
    constexpr int BS2 = BN + 8;

    __shared__ __align__(16) __half2 As[BM][AS2];
    __shared__ __align__(16) __half2 Bs[BK / 2][BS2];

    const int tid  = threadIdx.x;
    const int warp = tid >> 5;
    const int lane = tid & 31;
    const int wm = (warp % WARPS_M) * WM;
    const int wn = (warp / WARPS_M) * WN;
    const int rowBase = blockIdx.y * BM;
    const int colBase = blockIdx.x * BN;

    float acc[MFR][NFR][4];
#pragma unroll
    for (int i = 0; i < MFR; i++)
#pragma unroll
        for (int j = 0; j < NFR; j++)
#pragma unroll
            for (int q = 0; q < 4; q++) acc[i][j][q] = 0.f;

    const int arow = tid >> 1;
    const int acolh = (tid & 1) * 16;   // half offset
    const int brow = tid >> 3;
    const int bf40 = tid & 7;

    for (int k0 = 0; k0 < K; k0 += BK) {
        {
            const int gr = rowBase + arow;
            const __half* ap = A + (size_t)gr * K + k0 + acolh;
            uint4 q0 = make_uint4(0, 0, 0, 0), q1 = make_uint4(0, 0, 0, 0);
            if (gr < M) {
                q0 = *(const uint4*)ap;
                q1 = *(const uint4*)(ap + 8);
            }
            *(uint4*)&As[arow][acolh / 2 + 0] = q0;
            *(uint4*)&As[arow][acolh / 2 + 4] = q1;
        }
        {
            const float* bp = B + (size_t)(k0 + brow) * N + colBase;
            __half* bsh = (__half*)&Bs[brow >> 1][0];
            const int hsel = brow & 1;
#pragma unroll
            for (int i = 0; i < BN / 32; i++) {
                const int n = (bf40 + i * 8) * 4;
                float4 b = *(const float4*)(bp + n);
                bsh[(n + 0) * 2 + hsel] = __float2half_rn(b.x);
                bsh[(n + 1) * 2 + hsel] = __float2half_rn(b.y);
                bsh[(n + 2) * 2 + hsel] = __float2half_rn(b.z);
                bsh[(n + 3) * 2 + hsel] = __float2half_rn(b.w);
            }
        }
        __syncthreads();

#pragma unroll
        for (int ks = 0; ks < BK / 16; ks++) {
            uint32_t afr[MFR][4];
            uint32_t bfr[NFR][2];
            const int ar = wm + (lane >> 2);
            const int kb = ks * 8 + (lane & 3);
#pragma unroll
            for (int mi = 0; mi < MFR; mi++) {
                afr[mi][0] = *(const uint32_t*)&As[ar + mi * 16 + 0][kb + 0];
                afr[mi][1] = *(const uint32_t*)&As[ar + mi * 16 + 8][kb + 0];
                afr[mi][2] = *(const uint32_t*)&As[ar + mi * 16 + 0][kb + 4];
                afr[mi][3] = *(const uint32_t*)&As[ar + mi * 16 + 8][kb + 4];
            }
            const int bc = wn + (lane >> 2);
#pragma unroll
            for (int ni = 0; ni < NFR; ni++) {
                bfr[ni][0] = *(const uint32_t*)&Bs[kb + 0][bc + ni * 8];
                bfr[ni][1] = *(const uint32_t*)&Bs[kb + 4][bc + ni * 8];
            }
#pragma unroll
            for (int mi = 0; mi < MFR; mi++)
#pragma unroll
                for (int ni = 0; ni < NFR; ni++)
                    mma_f16(acc[mi][ni], afr[mi], bfr[ni]);
        }
        __syncthreads();
    }

#pragma unroll
    for (int mi = 0; mi < MFR; mi++) {
#pragma unroll
        for (int ni = 0; ni < NFR; ni++) {
            const int r0 = rowBase + wm + mi * 16 + (lane >> 2);
            const int c0 = colBase + wn + ni * 8 + 2 * (lane & 3);
            if (r0 < M)
                *(__half2*)(C + (size_t)r0 * N + c0) =
                    __floats2half2_rn(acc[mi][ni][0], acc[mi][ni][1]);
            if (r0 + 8 < M)
                *(__half2*)(C + (size_t)(r0 + 8) * N + c0) =
                    __floats2half2_rn(acc[mi][ni][2], acc[mi][ni][3]);
        }
    }
}

// ---------------------------------------------------------------------------
// CSR SpMM, F=256, fp16 source. One warp per row; each lane owns 8 halfs.
// Fused bias+relu; fp16 streaming output.
__global__ void spmm_csr_f256h(const __half* __restrict__ X, const float* __restrict__ bias,
                               __half* __restrict__ Y) {
    const int r = (blockIdx.x * blockDim.x + threadIdx.x) >> 5;
    const int lane = threadIdx.x & 31;
    if (r >= NNODE) return;
    const int start = g_rowptr[r];
    const int end   = g_rowptr[r + 1];
    float acc[8];
#pragma unroll
    for (int i = 0; i < 8; i++) acc[i] = 0.f;
    const uint4* Xb = (const uint4*)X + lane;  // row stride = 32 uint4
    for (int base = start; base < end; base += 32) {
        const int m = min(32, end - base);
        int2 ev = make_int2(0, 0);
        if (lane < m) ev = g_edges[base + lane];
#pragma unroll 4
        for (int j = 0; j < m; j++) {
            const int   cj = __shfl_sync(0xffffffffu, ev.x, j);
            const float vj = __int_as_float(__shfl_sync(0xffffffffu, ev.y, j));
            uint4 q = __ldg(Xb + (size_t)cj * 32);
            const __half2* hp = (const __half2*)&q;
#pragma unroll
            for (int i = 0; i < 4; i++) {
                float2 f = __half22float2(hp[i]);
                acc[i * 2 + 0] = fmaf(vj, f.x, acc[i * 2 + 0]);
                acc[i * 2 + 1] = fmaf(vj, f.y, acc[i * 2 + 1]);
            }
        }
    }
    float4 b0 = __ldg((const float4*)bias + lane * 2);
    float4 b1 = __ldg((const float4*)bias + lane * 2 + 1);
    float bb[8] = {b0.x, b0.y, b0.z, b0.w, b1.x, b1.y, b1.z, b1.w};
    __half2 o[4];
#pragma unroll
    for (int i = 0; i < 4; i++)
        o[i] = __floats2half2_rn(fmaxf(acc[i * 2] + bb[i * 2], 0.f),
                                 fmaxf(acc[i * 2 + 1] + bb[i * 2 + 1], 0.f));
    uint4 ov = *(const uint4*)o;
    stcs_u4((uint4*)Y + (size_t)r * 32 + lane, ov);
}

// CSR SpMM F=64 (fp16 source) fused with bias + log_softmax.
// One warp per row; lane owns classes {2*lane, 2*lane+1}.
__global__ void spmm_csr_f64h_ls(const __half* __restrict__ X, const float* __restrict__ bias,
                                 float* __restrict__ out) {
    const int r = (blockIdx.x * blockDim.x + threadIdx.x) >> 5;
    const int lane = threadIdx.x & 31;
    if (r >= NNODE) return;
    const int start = g_rowptr[r];
    const int end   = g_rowptr[r + 1];
    float2 acc = make_float2(0.f, 0.f);
    const uint32_t* Xb = (const uint32_t*)X + lane;  // row stride = 32 uint32
    for (int base = start; base < end; base += 32) {
        const int m = min(32, end - base);
        int2 ev = make_int2(0, 0);
        if (lane < m) ev = g_edges[base + lane];
#pragma unroll 4
        for (int j = 0; j < m; j++) {
            const int   cj = __shfl_sync(0xffffffffu, ev.x, j);
            const float vj = __int_as_float(__shfl_sync(0xffffffffu, ev.y, j));
            uint32_t q = __ldg(Xb + (size_t)cj * 32);
            float2 xs = __half22float2(*(const __half2*)&q);
            acc.x = fmaf(vj, xs.x, acc.x);
            acc.y = fmaf(vj, xs.y, acc.y);
        }
    }
    float2 bb = __ldg((const float2*)bias + lane);
    float v0 = acc.x + bb.x;
    float v1 = acc.y + bb.y;
    float mx = fmaxf(v0, v1);
#pragma unroll
    for (int o = 16; o; o >>= 1) mx = fmaxf(mx, __shfl_xor_sync(0xffffffffu, mx, o));
    float s = __expf(v0 - mx) + __expf(v1 - mx);
#pragma unroll
    for (int o = 16; o; o >>= 1) s += __shfl_xor_sync(0xffffffffu, s, o);
    float lse = mx + __logf(s);
    *(float2*)(out + (size_t)r * 64 + lane * 2) = make_float2(v0 - lse, v1 - lse);
}

// ---------------------------------------------------------------------------
extern "C" void kernel_launch(void* const* d_in, const int* in_sizes, int n_in,
                              void* d_out, int out_size) {
    const float* x    = (const float*)d_in[0];
    const int*   erow = (const int*)d_in[1];
    const int*   ecol = (const int*)d_in[2];
    const float* eval_ = (const float*)d_in[3];
    const float* W1   = (const float*)d_in[4];
    const float* b1   = (const float*)d_in[5];
    const float* W2   = (const float*)d_in[6];
    const float* b2   = (const float*)d_in[7];
    float* out = (float*)d_out;

    const int E = in_sizes[1];
    const int M = in_sizes[0] / NF;  // 100000

    __half *xw1, *h, *hw2;
    int *rowptr, *bsums;
    cudaGetSymbolAddress((void**)&xw1, g_xw1);
    cudaGetSymbolAddress((void**)&h, g_h);
    cudaGetSymbolAddress((void**)&hw2, g_hw2);
    cudaGetSymbolAddress((void**)&rowptr, g_rowptr);
    cudaGetSymbolAddress((void**)&bsums, g_bsums);

    const int L = NNODE + 1;
    const int nscan = (L + 1023) / 1024;  // 98

    // --- CSR build ---
    k_zero_csr<<<(NNODE + 256) / 256, 256>>>();
    k_hist<<<(E + 255) / 256, 256>>>(erow, E);
    k_scan_block<<<nscan, 256>>>(rowptr, L, bsums);
    k_scan_sums<<<1, 128>>>(bsums, nscan);
    k_scan_add<<<nscan, 256>>>(rowptr, L);
    k_scatter<<<(E + 255) / 256, 256>>>(erow, ecol, eval_, E);

    // layer 1: XW1 = x @ W1  (fp16 tensor cores, fp32 accum)
    f16_gemm_f32in<128, 2, 4><<<dim3(NH / 128, (M + 127) / 128), 256>>>(x, W1, xw1, M, NH, NF);

    // spmm1 (CSR gather, fp16 source L2-resident) + fused bias/relu
    {
        int blocks = (NNODE * 32 + 255) / 256;
        spmm_csr_f256h<<<blocks, 256>>>(xw1, b1, h);
    }

    // layer 2: HW2 = h @ W2  (fp16 tensor cores, fp16 A direct)
    f16_gemm_f16in<64, 4, 2><<<dim3(NC / 64, (M + 127) / 128), 256>>>(h, W2, hw2, M, NC, NH);

    // spmm2 (CSR gather, fp16 source) + fused bias + log_softmax
    {
        int blocks = (NNODE * 32 + 255) / 256;
        spmm_csr_f64h_ls<<<blocks, 256>>>(hw2, b2, out);
    }
}

// round 7
// speedup vs baseline: 4.0637x; 1.0749x over previous
#include <cuda_runtime.h>
#include <cuda_fp16.h>
#include <cstdint>

// Problem constants (shapes fixed by the reference)
constexpr int NF = 512;   // input features
constexpr int NH = 256;   // hidden
constexpr int NC = 64;    // classes
constexpr int NNODE = 100000;
constexpr int EMAX = 3200000;

// Scratch (allocation-free rule: __device__ globals)
__device__ __half g_xw1[(size_t)NNODE * NH];  // x @ W1 (fp16)
__device__ __half g_h[(size_t)NNODE * NH];    // spmm1 out / h (fp16)
__device__ __half g_hw2[(size_t)NNODE * NC];  // h @ W2 (fp16)
__device__ int    g_rowptr[NNODE + 1];
__device__ int    g_cursor[NNODE];
__device__ int2   g_edges[EMAX];              // (col, val-bits) sorted by row
__device__ int    g_bsums[128];

// ---------------------------------------------------------------------------
__device__ __forceinline__ void mma_f16(float c[4], const uint32_t a[4], const uint32_t b[2]) {
    asm volatile(
        "mma.sync.aligned.m16n8k16.row.col.f32.f16.f16.f32 "
        "{%0,%1,%2,%3}, {%4,%5,%6,%7}, {%8,%9}, {%0,%1,%2,%3};"
        : "+f"(c[0]), "+f"(c[1]), "+f"(c[2]), "+f"(c[3])
        : "r"(a[0]), "r"(a[1]), "r"(a[2]), "r"(a[3]), "r"(b[0]), "r"(b[1]));
}

__device__ __forceinline__ void stcs_u4(uint4* p, uint4 v) {
    asm volatile("st.global.cs.v4.u32 [%0], {%1,%2,%3,%4};"
                 :: "l"(p), "r"(v.x), "r"(v.y), "r"(v.z), "r"(v.w) : "memory");
}

// ---------------------------------------------------------------------------
// CSR build
__global__ void k_zero_csr() {
    int i = blockIdx.x * blockDim.x + threadIdx.x;
    if (i <= NNODE) g_rowptr[i] = 0;
    if (i < NNODE) g_cursor[i] = 0;
}

__global__ void k_hist(const int* __restrict__ rows, int E) {
    int e = blockIdx.x * blockDim.x + threadIdx.x;
    if (e < E) atomicAdd(&g_rowptr[rows[e] + 1], 1);
}

// inclusive block scan: 1024 elements per block (256 threads x 4)
__global__ void k_scan_block(int* __restrict__ d, int L, int* __restrict__ bsums) {
    __shared__ int warpsum[8];
    const int t = threadIdx.x, lane = t & 31, wid = t >> 5;
    const int base = blockIdx.x * 1024 + t * 4;
    int v0 = 0, v1 = 0, v2 = 0, v3 = 0;
    if (base + 3 < L) {
        int4 x = *(const int4*)(d + base);
        v0 = x.x; v1 = x.y; v2 = x.z; v3 = x.w;
    } else {
        if (base < L) v0 = d[base];
        if (base + 1 < L) v1 = d[base + 1];
        if (base + 2 < L) v2 = d[base + 2];
    }
    v1 += v0; v2 += v1; v3 += v2;
    int inc = v3;
#pragma unroll
    for (int o = 1; o < 32; o <<= 1) {
        int n = __shfl_up_sync(0xffffffffu, inc, o);
        if (lane >= o) inc += n;
    }
    if (lane == 31) warpsum[wid] = inc;
    __syncthreads();
    if (wid == 0) {
        int s = (lane < 8) ? warpsum[lane] : 0;
#pragma unroll
        for (int o = 1; o < 8; o <<= 1) {
            int n = __shfl_up_sync(0xffffffffu, s, o);
            if (lane >= o) s += n;
        }
        if (lane < 8) warpsum[lane] = s;
    }
    __syncthreads();
    int off = inc - v3;
    if (wid > 0) off += warpsum[wid - 1];
    v0 += off; v1 += off; v2 += off; v3 += off;
    if (base + 3 < L) {
        *(int4*)(d + base) = make_int4(v0, v1, v2, v3);
    } else {
        if (base < L) d[base] = v0;
        if (base + 1 < L) d[base + 1] = v1;
        if (base + 2 < L) d[base + 2] = v2;
    }
    if (t == 255) bsums[blockIdx.x] = v3;
}

__global__ void k_scan_sums(int* __restrict__ bsums, int nb) {
    __shared__ int ws[4];
    const int t = threadIdx.x, lane = t & 31, wid = t >> 5;
    int v = (t < nb) ? bsums[t] : 0;
    int inc = v;
#pragma unroll
    for (int o = 1; o < 32; o <<= 1) {
        int n = __shfl_up_sync(0xffffffffu, inc, o);
        if (lane >= o) inc += n;
    }
    if (lane == 31) ws[wid] = inc;
    __syncthreads();
    if (t == 0) {
        int run = 0;
#pragma unroll
        for (int i = 0; i < 4; i++) { int tmp = ws[i]; ws[i] = run; run += tmp; }
    }
    __syncthreads();
    int excl = inc - v + ws[wid];
    if (t < nb) bsums[t] = excl;
}

__global__ void k_scan_add(int* __restrict__ d, int L) {
    const int b = blockIdx.x;
    if (b == 0) return;
    const int add = g_bsums[b];
    const int base = b * 1024 + threadIdx.x * 4;
#pragma unroll
    for (int j = 0; j < 4; j++)
        if (base + j < L) d[base + j] += add;
}

__global__ void k_scatter(const int* __restrict__ rows, const int* __restrict__ cols,
                          const float* __restrict__ vals, int E) {
    int e = blockIdx.x * blockDim.x + threadIdx.x;
    if (e >= E) return;
    int r = rows[e];
    int idx = g_rowptr[r] + atomicAdd(&g_cursor[r], 1);
    g_edges[idx] = make_int2(cols[e], __float_as_int(vals[e]));
}

// ---------------------------------------------------------------------------
// FP16 GEMM (m16n8k16, fp32 accum), BM=128 x BN=256 x BK=32, 512 threads.
// A fp32 [M,512] read ONCE (whole N per block row). C fp16.
__global__ __launch_bounds__(512) void f16_gemm1(
        const float* __restrict__ A, const float* __restrict__ B,
        __half* __restrict__ C, int M, int N, int K) {
    constexpr int BM = 128;
    constexpr int BN = 256;
    constexpr int BK = 32;
    constexpr int WM = 32;       // 4 warps in M
    constexpr int WN = 64;       // 4 warps in N
    constexpr int MFR = 2;
    constexpr int NFR = 8;
    constexpr int AS2 = 20;      // half2 stride (16 data + 4 pad)
    constexpr int BS2 = BN + 8;  // 264

    __shared__ __align__(16) __half2 As[BM][AS2];
    __shared__ __align__(16) __half2 Bs[BK / 2][BS2];

    const int tid  = threadIdx.x;
    const int warp = tid >> 5;
    const int lane = tid & 31;
    const int wm = (warp & 3) * WM;
    const int wn = (warp >> 2) * WN;
    const int rowBase = blockIdx.y * BM;

    float acc[MFR][NFR][4];
#pragma unroll
    for (int i = 0; i < MFR; i++)
#pragma unroll
        for (int j = 0; j < NFR; j++)
#pragma unroll
            for (int q = 0; q < 4; q++) acc[i][j][q] = 0.f;

    // A: 128 rows x 32 cols fp32; 4 threads/row, 8 floats each
    const int arow = tid >> 2;
    const int acol0 = (tid & 3) * 8;
    // B: 32 rows x 256 cols fp32; 16 threads/row, 4 float4 each
    const int brow = tid >> 4;
    const int bf40 = tid & 15;

    for (int k0 = 0; k0 < K; k0 += BK) {
        {
            const int gr = rowBase + arow;
            const float* ap = A + (size_t)gr * K + k0 + acol0;
            float4 a0 = make_float4(0.f, 0.f, 0.f, 0.f);
            float4 a1 = make_float4(0.f, 0.f, 0.f, 0.f);
            if (gr < M) { a0 = *(const float4*)ap; a1 = *(const float4*)(ap + 4); }
            __half2 h[4];
            h[0] = __floats2half2_rn(a0.x, a0.y);
            h[1] = __floats2half2_rn(a0.z, a0.w);
            h[2] = __floats2half2_rn(a1.x, a1.y);
            h[3] = __floats2half2_rn(a1.z, a1.w);
            *(uint4*)&As[arow][acol0 / 2] = *(const uint4*)h;
        }
        {
            const float* bp = B + (size_t)(k0 + brow) * N;
            __half* bsh = (__half*)&Bs[brow >> 1][0];
            const int hsel = brow & 1;
#pragma unroll
            for (int i = 0; i < 4; i++) {
                const int n = (bf40 + i * 16) * 4;
                float4 b = *(const float4*)(bp + n);
                bsh[(n + 0) * 2 + hsel] = __float2half_rn(b.x);
                bsh[(n + 1) * 2 + hsel] = __float2half_rn(b.y);
                bsh[(n + 2) * 2 + hsel] = __float2half_rn(b.z);
                bsh[(n + 3) * 2 + hsel] = __float2half_rn(b.w);
            }
        }
        __syncthreads();

#pragma unroll
        for (int ks = 0; ks < BK / 16; ks++) {
            uint32_t afr[MFR][4];
            uint32_t bfr[NFR][2];
            const int ar = wm + (lane >> 2);
            const int kb = ks * 8 + (lane & 3);
#pragma unroll
            for (int mi = 0; mi < MFR; mi++) {
                afr[mi][0] = *(const uint32_t*)&As[ar + mi * 16 + 0][kb + 0];
                afr[mi][1] = *(const uint32_t*)&As[ar + mi * 16 + 8][kb + 0];
                afr[mi][2] = *(const uint32_t*)&As[ar + mi * 16 + 0][kb + 4];
                afr[mi][3] = *(const uint32_t*)&As[ar + mi * 16 + 8][kb + 4];
            }
            const int bc = wn + (lane >> 2);
#pragma unroll
            for (int ni = 0; ni < NFR; ni++) {
                bfr[ni][0] = *(const uint32_t*)&Bs[kb + 0][bc + ni * 8];
                bfr[ni][1] = *(const uint32_t*)&Bs[kb + 4][bc + ni * 8];
            }
#pragma unroll
            for (int mi = 0; mi < MFR; mi++)
#pragma unroll
                for (int ni = 0; ni < NFR; ni++)
                    mma_f16(acc[mi][ni], afr[mi], bfr[ni]);
        }
        __syncthreads();
    }

#pragma unroll
    for (int mi = 0; mi < MFR; mi++) {
#pragma unroll
        for (int ni = 0; ni < NFR; ni++) {
            const int r0 = rowBase + wm + mi * 16 + (lane >> 2);
            const int c0 = wn + ni * 8 + 2 * (lane & 3);
            if (r0 < M)
                *(__half2*)(C + (size_t)r0 * N + c0) =
                    __floats2half2_rn(acc[mi][ni][0], acc[mi][ni][1]);
            if (r0 + 8 < M)
                *(__half2*)(C + (size_t)(r0 + 8) * N + c0) =
                    __floats2half2_rn(acc[mi][ni][2], acc[mi][ni][3]);
        }
    }
}

// FP16 GEMM, fp16 A (direct copy), BM=128, BK=32, 256 threads.
template<int BN, int WARPS_M, int WARPS_N>
__global__ __launch_bounds__(256) void f16_gemm_f16in(
        const __half* __restrict__ A, const float* __restrict__ B,
        __half* __restrict__ C, int M, int N, int K) {
    constexpr int BM = 128;
    constexpr int BK = 32;
    constexpr int WM = BM / WARPS_M;
    constexpr int WN = BN / WARPS_N;
    constexpr int MFR = WM / 16;
    constexpr int NFR = WN / 8;
    constexpr int AS2 = 20;
    constexpr int BS2 = BN + 8;

    __shared__ __align__(16) __half2 As[BM][AS2];
    __shared__ __align__(16) __half2 Bs[BK / 2][BS2];

    const int tid  = threadIdx.x;
    const int warp = tid >> 5;
    const int lane = tid & 31;
    const int wm = (warp % WARPS_M) * WM;
    const int wn = (warp / WARPS_M) * WN;
    const int rowBase = blockIdx.y * BM;
    const int colBase = blockIdx.x * BN;

    float acc[MFR][NFR][4];
#pragma unroll
    for (int i = 0; i < MFR; i++)
#pragma unroll
        for (int j = 0; j < NFR; j++)
#pragma unroll
            for (int q = 0; q < 4; q++) acc[i][j][q] = 0.f;

    const int arow = tid >> 1;
    const int acolh = (tid & 1) * 16;
    const int brow = tid >> 3;
    const int bf40 = tid & 7;

    for (int k0 = 0; k0 < K; k0 += BK) {
        {
            const int gr = rowBase + arow;
            const __half* ap = A + (size_t)gr * K + k0 + acolh;
            uint4 q0 = make_uint4(0, 0, 0, 0), q1 = make_uint4(0, 0, 0, 0);
            if (gr < M) {
                q0 = *(const uint4*)ap;
                q1 = *(const uint4*)(ap + 8);
            }
            *(uint4*)&As[arow][acolh / 2 + 0] = q0;
            *(uint4*)&As[arow][acolh / 2 + 4] = q1;
        }
        {
            const float* bp = B + (size_t)(k0 + brow) * N + colBase;
            __half* bsh = (__half*)&Bs[brow >> 1][0];
            const int hsel = brow & 1;
#pragma unroll
            for (int i = 0; i < BN / 32; i++) {
                const int n = (bf40 + i * 8) * 4;
                float4 b = *(const float4*)(bp + n);
                bsh[(n + 0) * 2 + hsel] = __float2half_rn(b.x);
                bsh[(n + 1) * 2 + hsel] = __float2half_rn(b.y);
                bsh[(n + 2) * 2 + hsel] = __float2half_rn(b.z);
                bsh[(n + 3) * 2 + hsel] = __float2half_rn(b.w);
            }
        }
        __syncthreads();

#pragma unroll
        for (int ks = 0; ks < BK / 16; ks++) {
            uint32_t afr[MFR][4];
            uint32_t bfr[NFR][2];
            const int ar = wm + (lane >> 2);
            const int kb = ks * 8 + (lane & 3);
#pragma unroll
            for (int mi = 0; mi < MFR; mi++) {
                afr[mi][0] = *(const uint32_t*)&As[ar + mi * 16 + 0][kb + 0];
                afr[mi][1] = *(const uint32_t*)&As[ar + mi * 16 + 8][kb + 0];
                afr[mi][2] = *(const uint32_t*)&As[ar + mi * 16 + 0][kb + 4];
                afr[mi][3] = *(const uint32_t*)&As[ar + mi * 16 + 8][kb + 4];
            }
            const int bc = wn + (lane >> 2);
#pragma unroll
            for (int ni = 0; ni < NFR; ni++) {
                bfr[ni][0] = *(const uint32_t*)&Bs[kb + 0][bc + ni * 8];
                bfr[ni][1] = *(const uint32_t*)&Bs[kb + 4][bc + ni * 8];
            }
#pragma unroll
            for (int mi = 0; mi < MFR; mi++)
#pragma unroll
                for (int ni = 0; ni < NFR; ni++)
                    mma_f16(acc[mi][ni], afr[mi], bfr[ni]);
        }
        __syncthreads();
    }

#pragma unroll
    for (int mi = 0; mi < MFR; mi++) {
#pragma unroll
        for (int ni = 0; ni < NFR; ni++) {
            const int r0 = rowBase + wm + mi * 16 + (lane >> 2);
            const int c0 = colBase + wn + ni * 8 + 2 * (lane & 3);
            if (r0 < M)
                *(__half2*)(C + (size_t)r0 * N + c0) =
                    __floats2half2_rn(acc[mi][ni][0], acc[mi][ni][1]);
            if (r0 + 8 < M)
                *(__half2*)(C + (size_t)(r0 + 8) * N + c0) =
                    __floats2half2_rn(acc[mi][ni][2], acc[mi][ni][3]);
        }
    }
}

// ---------------------------------------------------------------------------
// CSR SpMM, F=256, fp16 source. One warp per row; each lane owns 8 halfs.
__global__ void spmm_csr_f256h(const __half* __restrict__ X, const float* __restrict__ bias,
                               __half* __restrict__ Y) {
    const int r = (blockIdx.x * blockDim.x + threadIdx.x) >> 5;
    const int lane = threadIdx.x & 31;
    if (r >= NNODE) return;
    const int start = g_rowptr[r];
    const int end   = g_rowptr[r + 1];
    float acc[8];
#pragma unroll
    for (int i = 0; i < 8; i++) acc[i] = 0.f;
    const uint4* Xb = (const uint4*)X + lane;
    for (int base = start; base < end; base += 32) {
        const int m = min(32, end - base);
        int2 ev = make_int2(0, 0);
        if (lane < m) ev = g_edges[base + lane];
#pragma unroll 4
        for (int j = 0; j < m; j++) {
            const int   cj = __shfl_sync(0xffffffffu, ev.x, j);
            const float vj = __int_as_float(__shfl_sync(0xffffffffu, ev.y, j));
            uint4 q = __ldg(Xb + (size_t)cj * 32);
            const __half2* hp = (const __half2*)&q;
#pragma unroll
            for (int i = 0; i < 4; i++) {
                float2 f = __half22float2(hp[i]);
                acc[i * 2 + 0] = fmaf(vj, f.x, acc[i * 2 + 0]);
                acc[i * 2 + 1] = fmaf(vj, f.y, acc[i * 2 + 1]);
            }
        }
    }
    float4 b0 = __ldg((const float4*)bias + lane * 2);
    float4 b1 = __ldg((const float4*)bias + lane * 2 + 1);
    float bb[8] = {b0.x, b0.y, b0.z, b0.w, b1.x, b1.y, b1.z, b1.w};
    __half2 o[4];
#pragma unroll
    for (int i = 0; i < 4; i++)
        o[i] = __floats2half2_rn(fmaxf(acc[i * 2] + bb[i * 2], 0.f),
                                 fmaxf(acc[i * 2 + 1] + bb[i * 2 + 1], 0.f));
    uint4 ov = *(const uint4*)o;
    stcs_u4((uint4*)Y + (size_t)r * 32 + lane, ov);
}

// CSR SpMM F=64 (fp16 source) fused with bias + log_softmax.
__global__ void spmm_csr_f64h_ls(const __half* __restrict__ X, const float* __restrict__ bias,
                                 float* __restrict__ out) {
    const int r = (blockIdx.x * blockDim.x + threadIdx.x) >> 5;
    const int lane = threadIdx.x & 31;
    if (r >= NNODE) return;
    const int start = g_rowptr[r];
    const int end   = g_rowptr[r + 1];
    float2 acc = make_float2(0.f, 0.f);
    const uint32_t* Xb = (const uint32_t*)X + lane;
    for (int base = start; base < end; base += 32) {
        const int m = min(32, end - base);
        int2 ev = make_int2(0, 0);
        if (lane < m) ev = g_edges[base + lane];
#pragma unroll 4
        for (int j = 0; j < m; j++) {
            const int   cj = __shfl_sync(0xffffffffu, ev.x, j);
            const float vj = __int_as_float(__shfl_sync(0xffffffffu, ev.y, j));
            uint32_t q = __ldg(Xb + (size_t)cj * 32);
            float2 xs = __half22float2(*(const __half2*)&q);
            acc.x = fmaf(vj, xs.x, acc.x);
            acc.y = fmaf(vj, xs.y, acc.y);
        }
    }
    float2 bb = __ldg((const float2*)bias + lane);
    float v0 = acc.x + bb.x;
    float v1 = acc.y + bb.y;
    float mx = fmaxf(v0, v1);
#pragma unroll
    for (int o = 16; o; o >>= 1) mx = fmaxf(mx, __shfl_xor_sync(0xffffffffu, mx, o));
    float s = __expf(v0 - mx) + __expf(v1 - mx);
#pragma unroll
    for (int o = 16; o; o >>= 1) s += __shfl_xor_sync(0xffffffffu, s, o);
    float lse = mx + __logf(s);
    *(float2*)(out + (size_t)r * 64 + lane * 2) = make_float2(v0 - lse, v1 - lse);
}

// ---------------------------------------------------------------------------
extern "C" void kernel_launch(void* const* d_in, const int* in_sizes, int n_in,
                              void* d_out, int out_size) {
    const float* x    = (const float*)d_in[0];
    const int*   erow = (const int*)d_in[1];
    const int*   ecol = (const int*)d_in[2];
    const float* eval_ = (const float*)d_in[3];
    const float* W1   = (const float*)d_in[4];
    const float* b1   = (const float*)d_in[5];
    const float* W2   = (const float*)d_in[6];
    const float* b2   = (const float*)d_in[7];
    float* out = (float*)d_out;

    const int E = in_sizes[1];
    const int M = in_sizes[0] / NF;  // 100000

    __half *xw1, *h, *hw2;
    int *rowptr, *bsums;
    cudaGetSymbolAddress((void**)&xw1, g_xw1);
    cudaGetSymbolAddress((void**)&h, g_h);
    cudaGetSymbolAddress((void**)&hw2, g_hw2);
    cudaGetSymbolAddress((void**)&rowptr, g_rowptr);
    cudaGetSymbolAddress((void**)&bsums, g_bsums);

    const int L = NNODE + 1;
    const int nscan = (L + 1023) / 1024;  // 98

    // One-time side resources (host-side only; no device memory involved).
    static cudaStream_t s2 = nullptr;
    static cudaEvent_t evFork = nullptr, evJoin = nullptr;
    if (!s2) {
        cudaStreamCreateWithFlags(&s2, cudaStreamNonBlocking);
        cudaEventCreateWithFlags(&evFork, cudaEventDisableTiming);
        cudaEventCreateWithFlags(&evJoin, cudaEventDisableTiming);
    }

    // Fork: CSR build on s2, concurrent with GEMM1 on the main stream.
    cudaEventRecord(evFork, 0);
    cudaStreamWaitEvent(s2, evFork, 0);

    // --- CSR build (stream s2) ---
    k_zero_csr<<<(NNODE + 256) / 256, 256, 0, s2>>>();
    k_hist<<<(E + 255) / 256, 256, 0, s2>>>(erow, E);
    k_scan_block<<<nscan, 256, 0, s2>>>(rowptr, L, bsums);
    k_scan_sums<<<1, 128, 0, s2>>>(bsums, nscan);
    k_scan_add<<<nscan, 256, 0, s2>>>(rowptr, L);
    k_scatter<<<(E + 255) / 256, 256, 0, s2>>>(erow, ecol, eval_, E);
    cudaEventRecord(evJoin, s2);

    // --- layer 1 GEMM (main stream, concurrent with CSR build) ---
    f16_gemm1<<<dim3(1, (M + 127) / 128), 512>>>(x, W1, xw1, M, NH, NF);

    // Join: spmm1 needs both GEMM1 and the CSR structures.
    cudaStreamWaitEvent(0, evJoin, 0);

    // spmm1 (CSR gather, fp16 source L2-resident) + fused bias/relu
    {
        int blocks = (NNODE * 32 + 255) / 256;
        spmm_csr_f256h<<<blocks, 256>>>(xw1, b1, h);
    }

    // layer 2: HW2 = h @ W2  (fp16 tensor cores, fp16 A direct)
    f16_gemm_f16in<64, 4, 2><<<dim3(NC / 64, (M + 127) / 128), 256>>>(h, W2, hw2, M, NC, NH);

    // spmm2 (CSR gather, fp16 source) + fused bias + log_softmax
    {
        int blocks = (NNODE * 32 + 255) / 256;
        spmm_csr_f64h_ls<<<blocks, 256>>>(hw2, b2, out);
    }
}